// round 9
// baseline (speedup 1.0000x reference)
#include <cuda_runtime.h>
#include <math.h>
#include <stdint.h>

#define NB   128
#define NS1  16
#define NDQ  300
#define NC   256
#define NS2  8
#define ND   256
#define MQ   (NB*NS1) // 2048
#define MK   (NC*NS2) // 2048

struct alignas(128) Scratch {
    float Q[MQ * ND];
    float K[MK * ND];
    float V[MK * ND];
    float abar[(size_t)NB * NC * NS2];  // 128x256x8
    float proto[(size_t)NB * NC * ND];  // 128x256x256
    float center[NB * ND];
    float nd[NB * ND];
    float invn[NB * NC];
    float ce[NB];
    float rm1p[(size_t)NB * 4 * NC];    // per-b, per-64col-slot partial rowmax
    float rm2[NB];
};
__device__ Scratch g_scratch;

// ---------------------------------------------------------------------------
// helpers
// ---------------------------------------------------------------------------
__device__ __forceinline__ uint32_t f2tf32(float x) {
    uint32_t r;
    asm("cvt.rna.tf32.f32 %0, %1;" : "=r"(r) : "f"(x));
    return r;
}
__device__ __forceinline__ void mma_tf32(float* d, const uint32_t* a, uint32_t b0, uint32_t b1) {
    asm volatile(
        "mma.sync.aligned.m16n8k8.row.col.f32.tf32.tf32.f32 "
        "{%0,%1,%2,%3},{%4,%5,%6,%7},{%8,%9},{%0,%1,%2,%3};"
        : "+f"(d[0]), "+f"(d[1]), "+f"(d[2]), "+f"(d[3])
        : "r"(a[0]), "r"(a[1]), "r"(a[2]), "r"(a[3]), "r"(b0), "r"(b1));
}

// exp(x) for x <= 0, FMA pipe only.
__device__ __forceinline__ float fexp(float x) {
    x = fmaxf(x, -80.f);
    const float L2E = 1.4426950408889634f;
    float t = fmaf(x, L2E, 12582912.f);
    float n = t - 12582912.f;
    float f = fmaf(x, L2E, -n);
    float p = 0.0001540353f;
    p = fmaf(p, f, 0.0013333558f);
    p = fmaf(p, f, 0.0096181291f);
    p = fmaf(p, f, 0.0555041087f);
    p = fmaf(p, f, 0.2402265069f);
    p = fmaf(p, f, 0.6931471806f);
    p = fmaf(p, f, 1.0f);
    int ni = (__float_as_int(t) & 0x7FFFFF) - 0x400000;
    return __int_as_float((ni + 127) << 23) * p;
}
__device__ __forceinline__ float frcp(float x) {
    float r = __uint_as_float(0x7EF311C3u - __float_as_uint(x));
    r = r * (2.f - x * r);
    r = r * (2.f - x * r);
    r = r * (2.f - x * r);
    return r;
}

#define GSTR 12

// ---------------------------------------------------------------------------
// Merged QKV projection: one launch, blockIdx.z selects {Q,K,V}.
// 64x64 tiles, 4x4 micro (round-5-validated body). grid (4, 32, 3).
// ---------------------------------------------------------------------------
__global__ void qkv_proj(const float* __restrict__ drug, const float* __restrict__ sem,
                         const float* __restrict__ Wq, const float* __restrict__ Wk,
                         const float* __restrict__ Wv, float* __restrict__ Qo,
                         float* __restrict__ Ko, float* __restrict__ Vo) {
    int z = blockIdx.z;
    const float* A = (z == 0) ? drug : sem;
    const float* B = (z == 0) ? Wq : ((z == 1) ? Wk : Wv);
    float* C = (z == 0) ? Qo : ((z == 1) ? Ko : Vo);
    int K = (z == 0) ? NDQ : ND;
    const int N = ND;

    __shared__ float As[64][17];
    __shared__ float Bs[64][17];
    int tid = threadIdx.x;
    int tx = tid & 15, ty = tid >> 4;
    int m0 = blockIdx.y * 64, n0 = blockIdx.x * 64;
    float acc[4][4];
#pragma unroll
    for (int i = 0; i < 4; i++)
#pragma unroll
        for (int j = 0; j < 4; j++) acc[i][j] = 0.f;
    for (int k0 = 0; k0 < K; k0 += 16) {
#pragma unroll
        for (int i = 0; i < 4; i++) {
            int idx = tid + 256 * i;
            int r = idx >> 4, kk = idx & 15;
            int kg = k0 + kk;
            As[r][kk] = (kg < K) ? A[(size_t)(m0 + r) * K + kg] : 0.f;
        }
#pragma unroll
        for (int i = 0; i < 4; i++) {
            int idx = tid + 256 * i;
            int kk = idx >> 6, n = idx & 63;
            int kg = k0 + kk;
            Bs[n][kk] = (kg < K) ? B[(size_t)kg * N + n0 + n] : 0.f;
        }
        __syncthreads();
#pragma unroll
        for (int kk = 0; kk < 16; kk++) {
            float a[4], bb[4];
#pragma unroll
            for (int i = 0; i < 4; i++) a[i] = As[ty * 4 + i][kk];
#pragma unroll
            for (int j = 0; j < 4; j++) bb[j] = Bs[tx * 4 + j][kk];
#pragma unroll
            for (int i = 0; i < 4; i++)
#pragma unroll
                for (int j = 0; j < 4; j++) acc[i][j] += a[i] * bb[j];
        }
        __syncthreads();
    }
#pragma unroll
    for (int i = 0; i < 4; i++)
#pragma unroll
        for (int j = 0; j < 4; j++)
            C[(size_t)(m0 + ty * 4 + i) * N + n0 + tx * 4 + j] = acc[i][j];
}

// ---------------------------------------------------------------------------
// FUSED scores (tf32) + softmax(s2) + mean(s1) -> abar. Tile 128x64.
// grid (32, 16), 256 threads; warps 4 row x 2 col, each warp 32r x 32c.
// ---------------------------------------------------------------------------
__global__ __launch_bounds__(256) void scores_abar_tf32(const float* __restrict__ A,
                                                        const float* __restrict__ B,
                                                        float* __restrict__ abar, float alpha) {
    __shared__ uint32_t Ah[128 * GSTR];
    __shared__ uint32_t Bh[64 * GSTR];

    int m0 = blockIdx.y * 128, n0 = blockIdx.x * 64;
    int t = threadIdx.x;
    int w = t >> 5, lane = t & 31;
    int w_row = w >> 1, w_col = w & 1;
    int qrow = lane >> 2, qcol = lane & 3;
    int lrow = t >> 1, lpart = (t & 1) * 4;      // A loader: 128 rows x 2 thr
    int brow = t >> 2, bpart = (t & 3) * 2;      // B loader: 64 rows x 4 thr

    const float* Ag = A + (size_t)(m0 + lrow) * ND + lpart;
    const float* Bg = B + (size_t)(n0 + brow) * ND + bpart;

    float acc[2][4][4];
#pragma unroll
    for (int mi = 0; mi < 2; mi++)
#pragma unroll
        for (int nt = 0; nt < 4; nt++)
#pragma unroll
            for (int j = 0; j < 4; j++) acc[mi][nt][j] = 0.f;

    float4 pa = *(const float4*)(Ag);
    float2 pb = *(const float2*)(Bg);

    for (int k0 = 0; k0 < ND; k0 += 8) {
        uint32_t* ad = &Ah[lrow * GSTR + lpart];
        ad[0] = f2tf32(pa.x); ad[1] = f2tf32(pa.y);
        ad[2] = f2tf32(pa.z); ad[3] = f2tf32(pa.w);
        uint32_t* bd = &Bh[brow * GSTR + bpart];
        bd[0] = f2tf32(pb.x); bd[1] = f2tf32(pb.y);
        __syncthreads();
        if (k0 + 8 < ND) {
            pa = *(const float4*)(Ag + k0 + 8);
            pb = *(const float2*)(Bg + k0 + 8);
        }
        uint32_t afr[2][4];
#pragma unroll
        for (int mi = 0; mi < 2; mi++) {
            int mr = w_row * 32 + mi * 16 + qrow;
            afr[mi][0] = Ah[mr * GSTR + qcol];
            afr[mi][1] = Ah[(mr + 8) * GSTR + qcol];
            afr[mi][2] = Ah[mr * GSTR + qcol + 4];
            afr[mi][3] = Ah[(mr + 8) * GSTR + qcol + 4];
        }
#pragma unroll
        for (int nt = 0; nt < 4; nt++) {
            int nr = w_col * 32 + nt * 8 + qrow;
            uint32_t b0 = Bh[nr * GSTR + qcol];
            uint32_t b1 = Bh[nr * GSTR + qcol + 4];
            mma_tf32(acc[0][nt], afr[0], b0, b1);
            mma_tf32(acc[1][nt], afr[1], b0, b1);
        }
        __syncthreads();
    }

    const float inv16 = 1.f / 16.f;
#pragma unroll
    for (int mi = 0; mi < 2; mi++) {
        int b = (m0 >> 4) + w_row * 2 + mi;
#pragma unroll
        for (int nt = 0; nt < 4; nt++) {
            int c = (n0 >> 3) + w_col * 4 + nt;
            float v00 = acc[mi][nt][0] * alpha;
            float v01 = acc[mi][nt][1] * alpha;
            float v10 = acc[mi][nt][2] * alpha;
            float v11 = acc[mi][nt][3] * alpha;
            float mx0 = fmaxf(v00, v01), mx1 = fmaxf(v10, v11);
            mx0 = fmaxf(mx0, __shfl_xor_sync(0xffffffffu, mx0, 1));
            mx0 = fmaxf(mx0, __shfl_xor_sync(0xffffffffu, mx0, 2));
            mx1 = fmaxf(mx1, __shfl_xor_sync(0xffffffffu, mx1, 1));
            mx1 = fmaxf(mx1, __shfl_xor_sync(0xffffffffu, mx1, 2));
            float e00 = fexp(v00 - mx0), e01 = fexp(v01 - mx0);
            float e10 = fexp(v10 - mx1), e11 = fexp(v11 - mx1);
            float s0 = e00 + e01, s1 = e10 + e11;
            s0 += __shfl_xor_sync(0xffffffffu, s0, 1);
            s0 += __shfl_xor_sync(0xffffffffu, s0, 2);
            s1 += __shfl_xor_sync(0xffffffffu, s1, 1);
            s1 += __shfl_xor_sync(0xffffffffu, s1, 2);
            float r0 = frcp(s0), r1 = frcp(s1);
            float a0 = e00 * r0 + e10 * r1;
            float a1 = e01 * r0 + e11 * r1;
            a0 += __shfl_xor_sync(0xffffffffu, a0, 4);
            a1 += __shfl_xor_sync(0xffffffffu, a1, 4);
            a0 += __shfl_xor_sync(0xffffffffu, a0, 8);
            a1 += __shfl_xor_sync(0xffffffffu, a1, 8);
            a0 += __shfl_xor_sync(0xffffffffu, a0, 16);
            a1 += __shfl_xor_sync(0xffffffffu, a1, 16);
            if (qrow == 0) {
                float2 v = make_float2(a0 * inv16, a1 * inv16);
                *(float2*)&abar[((size_t)b * NC + c) * 8 + qcol * 2] = v;
            }
        }
    }
}

// ---------------------------------------------------------------------------
// proto[b,c,:] = sum_t abar[b,c,t] * V[c,t,:]. grid (256 c, 4 btile), 256 thr.
// ---------------------------------------------------------------------------
__global__ void proto_kernel(const float* __restrict__ abar, const float* __restrict__ V,
                             float* __restrict__ proto) {
    int c = blockIdx.x;
    int bt = blockIdx.y;
    int t = threadIdx.x;
    __shared__ float Vs[8][256];
    __shared__ float ab[32][8];

    for (int i = t; i < 8 * 256; i += 256)
        Vs[i >> 8][i & 255] = V[(size_t)c * 8 * 256 + i];
    {
        int bl = t >> 3, j = t & 7;
        ab[bl][j] = abar[((size_t)(bt * 32 + bl) * NC + c) * 8 + j];
    }
    __syncthreads();

#pragma unroll 4
    for (int bl = 0; bl < 32; bl++) {
        float a0 = ab[bl][0], a1 = ab[bl][1], a2 = ab[bl][2], a3 = ab[bl][3];
        float a4 = ab[bl][4], a5 = ab[bl][5], a6 = ab[bl][6], a7 = ab[bl][7];
        float acc = a0 * Vs[0][t] + a1 * Vs[1][t] + a2 * Vs[2][t] + a3 * Vs[3][t]
                  + a4 * Vs[4][t] + a5 * Vs[5][t] + a6 * Vs[6][t] + a7 * Vs[7][t];
        proto[((size_t)(bt * 32 + bl) * NC + c) * ND + t] = acc;
    }
}

// ---------------------------------------------------------------------------
// tf32 Gram + rowmax, SYMMETRIC, 128x64 tiles. grid (6, 128 b), 256 thr.
// Tiles: (r0,c0) in {(0,0),(0,64),(0,128),(0,192),(128,128),(128,192)}.
// Tiles 2,3 (r0=0, c0>=128) also emit colmax = transposed rowmax for
// rows c0..c0+63 over cols 0..127, written to slots 0 AND 1.
// rm1p layout: [b][slot 0..3][256] where slot = c0/64 for direct rows.
// ---------------------------------------------------------------------------
__global__ __launch_bounds__(256) void gram_rowmax_tf32(const float* __restrict__ proto,
                                                        const float* __restrict__ center,
                                                        const float* __restrict__ invn,
                                                        float* __restrict__ rm1p) {
    __shared__ uint32_t As[128 * GSTR];
    __shared__ uint32_t Bs[64 * GSTR];
    __shared__ float rmax_s[2][128];
    __shared__ float cmax_s[4][64];

    const int r0s[6] = {0, 0, 0, 0, 128, 128};
    const int c0s[6] = {0, 64, 128, 192, 128, 192};
    int tri = blockIdx.x;
    int b = blockIdx.y;
    int r0 = r0s[tri], c0 = c0s[tri];
    bool offdiag = (tri == 2 || tri == 3);

    const float* X = proto + (size_t)b * NC * ND;
    const float* ctr = center + b * ND;

    int t = threadIdx.x;
    int w = t >> 5, lane = t & 31;
    int w_row = w >> 1, w_col = w & 1;
    int qrow = lane >> 2, qcol = lane & 3;
    int lrow = t >> 1, lpart = (t & 1) * 4;
    int brow = t >> 2, bpart = (t & 3) * 2;

    const float* Ag = X + (size_t)(r0 + lrow) * ND + lpart;
    const float* Bg = X + (size_t)(c0 + brow) * ND + bpart;

    float acc[2][4][4];
#pragma unroll
    for (int mi = 0; mi < 2; mi++)
#pragma unroll
        for (int nt = 0; nt < 4; nt++)
#pragma unroll
            for (int j = 0; j < 4; j++) acc[mi][nt][j] = 0.f;

    float4 pa = *(const float4*)(Ag);
    float2 pb = *(const float2*)(Bg);
    float4 pca = *(const float4*)(ctr + lpart);
    float2 pcb = *(const float2*)(ctr + bpart);

    for (int k0 = 0; k0 < ND; k0 += 8) {
        uint32_t* ad = &As[lrow * GSTR + lpart];
        ad[0] = f2tf32(pa.x - pca.x); ad[1] = f2tf32(pa.y - pca.y);
        ad[2] = f2tf32(pa.z - pca.z); ad[3] = f2tf32(pa.w - pca.w);
        uint32_t* bd = &Bs[brow * GSTR + bpart];
        bd[0] = f2tf32(pb.x - pcb.x); bd[1] = f2tf32(pb.y - pcb.y);
        __syncthreads();
        if (k0 + 8 < ND) {
            pa = *(const float4*)(Ag + k0 + 8);
            pb = *(const float2*)(Bg + k0 + 8);
            pca = *(const float4*)(ctr + k0 + 8 + lpart);
            pcb = *(const float2*)(ctr + k0 + 8 + bpart);
        }
        uint32_t afr[2][4];
#pragma unroll
        for (int mi = 0; mi < 2; mi++) {
            int mr = w_row * 32 + mi * 16 + qrow;
            afr[mi][0] = As[mr * GSTR + qcol];
            afr[mi][1] = As[(mr + 8) * GSTR + qcol];
            afr[mi][2] = As[mr * GSTR + qcol + 4];
            afr[mi][3] = As[(mr + 8) * GSTR + qcol + 4];
        }
#pragma unroll
        for (int nt = 0; nt < 4; nt++) {
            int nr = w_col * 32 + nt * 8 + qrow;
            uint32_t b0 = Bs[nr * GSTR + qcol];
            uint32_t b1 = Bs[nr * GSTR + qcol + 4];
            mma_tf32(acc[0][nt], afr[0], b0, b1);
            mma_tf32(acc[1][nt], afr[1], b0, b1);
        }
        __syncthreads();
    }

    const float* invb = invn + b * NC;
    float ir[2][2];
#pragma unroll
    for (int mi = 0; mi < 2; mi++) {
        int r = r0 + w_row * 32 + mi * 16 + qrow;
        ir[mi][0] = invb[r];
        ir[mi][1] = invb[r + 8];
    }
    float ic[4][2];
#pragma unroll
    for (int nt = 0; nt < 4; nt++) {
        int c = c0 + w_col * 32 + nt * 8 + qcol * 2;
        ic[nt][0] = invb[c];
        ic[nt][1] = invb[c + 1];
    }
    float rmx[2][2] = {{-1e30f, -1e30f}, {-1e30f, -1e30f}};
    float cm[4][2];
#pragma unroll
    for (int nt = 0; nt < 4; nt++) { cm[nt][0] = -1e30f; cm[nt][1] = -1e30f; }

#pragma unroll
    for (int mi = 0; mi < 2; mi++)
#pragma unroll
        for (int h = 0; h < 2; h++) {
            int r = r0 + w_row * 32 + mi * 16 + qrow + h * 8;
#pragma unroll
            for (int nt = 0; nt < 4; nt++) {
#pragma unroll
                for (int j = 0; j < 2; j++) {
                    int c = c0 + w_col * 32 + nt * 8 + qcol * 2 + j;
                    float v = acc[mi][nt][h * 2 + j] * ir[mi][h] * ic[nt][j] - (r == c ? 1.f : 0.f);
                    rmx[mi][h] = fmaxf(rmx[mi][h], v);
                    cm[nt][j] = fmaxf(cm[nt][j], v);
                }
            }
        }
    // rowmax: reduce over quad cols
#pragma unroll
    for (int off = 1; off < 4; off <<= 1)
#pragma unroll
        for (int mi = 0; mi < 2; mi++)
#pragma unroll
            for (int h = 0; h < 2; h++)
                rmx[mi][h] = fmaxf(rmx[mi][h], __shfl_xor_sync(0xffffffffu, rmx[mi][h], off));
    if (qcol == 0) {
#pragma unroll
        for (int mi = 0; mi < 2; mi++)
#pragma unroll
            for (int h = 0; h < 2; h++)
                rmax_s[w_col][w_row * 32 + mi * 16 + qrow + h * 8] = rmx[mi][h];
    }
    if (offdiag) {
        // colmax: reduce over the 8 qrow groups
#pragma unroll
        for (int off = 4; off < 32; off <<= 1)
#pragma unroll
            for (int nt = 0; nt < 4; nt++)
#pragma unroll
                for (int j = 0; j < 2; j++)
                    cm[nt][j] = fmaxf(cm[nt][j], __shfl_xor_sync(0xffffffffu, cm[nt][j], off));
        if (qrow == 0) {
#pragma unroll
            for (int nt = 0; nt < 4; nt++)
#pragma unroll
                for (int j = 0; j < 2; j++)
                    cmax_s[w_row][w_col * 32 + nt * 8 + qcol * 2 + j] = cm[nt][j];
        }
    }
    __syncthreads();
    float* rb = rm1p + (size_t)b * 4 * NC;
    if (t < 128)
        rb[(c0 >> 6) * NC + r0 + t] = fmaxf(rmax_s[0][t], rmax_s[1][t]);
    if (offdiag && t < 64) {
        float v = fmaxf(fmaxf(cmax_s[0][t], cmax_s[1][t]), fmaxf(cmax_s[2][t], cmax_s[3][t]));
        rb[0 * NC + c0 + t] = v;
        rb[1 * NC + c0 + t] = v;
    }
}

// ---------------------------------------------------------------------------
// Per-b: center, n_d, logits, CE, invn fused. grid 128, 256 thr.
// ---------------------------------------------------------------------------
__global__ void logits_center_ce(const float* __restrict__ proto, const float* __restrict__ left,
                                 const int* __restrict__ ids, float* __restrict__ center,
                                 float* __restrict__ nd, float* __restrict__ ce_part,
                                 float* __restrict__ invn) {
    int b = blockIdx.x;
    int t = threadIdx.x;
    __shared__ float red[256];
    __shared__ float lf[256];
    __shared__ float cf[256];
    __shared__ float lgs[256];
    const float* pb = proto + (size_t)b * 65536;

    float s = 0.f;
    for (int c = 0; c < 256; c++) s += pb[(size_t)c * 256 + t];
    float ctr = s * (1.f / 256.f);
    center[b * 256 + t] = ctr;
    cf[t] = ctr;

    float lv = left[b * 256 + t];
    lf[t] = lv;

    float v = lv - ctr;
    red[t] = v * v;
    __syncthreads();
    for (int off = 128; off > 0; off >>= 1) {
        if (t < off) red[t] += red[t + off];
        __syncthreads();
    }
    float nrm = sqrtf(red[0]);
    nd[b * 256 + t] = v / fmaxf(nrm, 1e-12f);
    __syncthreads();

    int w = t >> 5, lane = t & 31;
    float4 l0 = *(const float4*)&lf[lane * 8];
    float4 l1 = *(const float4*)&lf[lane * 8 + 4];
    float4 c0 = *(const float4*)&cf[lane * 8];
    float4 c1 = *(const float4*)&cf[lane * 8 + 4];
    for (int cc = 0; cc < 32; cc++) {
        int c = w * 32 + cc;
        const float* pr = pb + (size_t)c * 256 + lane * 8;
        float4 x0 = *(const float4*)pr;
        float4 x1 = *(const float4*)(pr + 4);
        float d = x0.x * l0.x + x0.y * l0.y + x0.z * l0.z + x0.w * l0.w
                + x1.x * l1.x + x1.y * l1.y + x1.z * l1.z + x1.w * l1.w;
        float dx, sq = 0.f;
        dx = x0.x - c0.x; sq += dx * dx;
        dx = x0.y - c0.y; sq += dx * dx;
        dx = x0.z - c0.z; sq += dx * dx;
        dx = x0.w - c0.w; sq += dx * dx;
        dx = x1.x - c1.x; sq += dx * dx;
        dx = x1.y - c1.y; sq += dx * dx;
        dx = x1.z - c1.z; sq += dx * dx;
        dx = x1.w - c1.w; sq += dx * dx;
#pragma unroll
        for (int off = 16; off > 0; off >>= 1) {
            d += __shfl_xor_sync(0xffffffffu, d, off);
            sq += __shfl_xor_sync(0xffffffffu, sq, off);
        }
        if (lane == 0) {
            lgs[c] = d * (1.0f / 0.9f);
            invn[b * NC + c] = 1.f / fmaxf(sqrtf(sq), 1e-12f);
        }
    }
    __syncthreads();

    float lg = lgs[t];
    red[t] = lg;
    __syncthreads();
    for (int off = 128; off > 0; off >>= 1) {
        if (t < off) red[t] = fmaxf(red[t], red[t + off]);
        __syncthreads();
    }
    float mx = red[0];
    __syncthreads();
    red[t] = expf(lg - mx);
    __syncthreads();
    for (int off = 128; off > 0; off >>= 1) {
        if (t < off) red[t] += red[t + off];
        __syncthreads();
    }
    if (t == 0) {
        float lse = mx + logf(red[0]);
        ce_part[b] = lse - lgs[ids[b]];
    }
}

// ---------------------------------------------------------------------------
__global__ void dcos_rowmax(const float* __restrict__ nd, float* __restrict__ rowmax2) {
    int i = blockIdx.x;
    int t = threadIdx.x;
    __shared__ float xi[256];
    __shared__ float red[256];
    xi[t] = nd[i * 256 + t];
    __syncthreads();
    float m = -1e30f;
    if (t < 128) {
        float s = 0.f;
        const float* xj = nd + t * 256;
        for (int d = 0; d < 256; d++) s += xi[d] * xj[d];
        m = s - (i == t ? 1.f : 0.f);
    }
    red[t] = m;
    __syncthreads();
    for (int off = 128; off > 0; off >>= 1) {
        if (t < off) red[t] = fmaxf(red[t], red[t + off]);
        __syncthreads();
    }
    if (t == 0) rowmax2[i] = red[0];
}

// ---------------------------------------------------------------------------
__global__ void finalize(const float* __restrict__ ce_part, const float* __restrict__ rm1p,
                         const float* __restrict__ rm2, float* __restrict__ out, int out_size) {
    int t = threadIdx.x;
    __shared__ float ra[256], rb2[256], rc[256];
    float a = 0.f, b2 = 0.f, c2 = 0.f;
    for (int i = t; i < 128; i += 256) { a += ce_part[i]; c2 += rm2[i]; }
    for (int i = t; i < 32768; i += 256) {
        int b = i >> 8, r = i & 255;
        const float* rbp = rm1p + (size_t)b * 4 * NC;
        float v = fmaxf(fmaxf(rbp[0 * NC + r], rbp[1 * NC + r]),
                        fmaxf(rbp[2 * NC + r], rbp[3 * NC + r]));
        b2 += v;
    }
    ra[t] = a; rb2[t] = b2; rc[t] = c2;
    __syncthreads();
    for (int off = 128; off > 0; off >>= 1) {
        if (t < off) {
            ra[t] += ra[t + off];
            rb2[t] += rb2[t + off];
            rc[t] += rc[t + off];
        }
        __syncthreads();
    }
    if (t == 0) {
        float loss = ra[0] / 128.f + 0.7f * (rb2[0] / 32768.f + rc[0] / 128.f);
        for (int i = 0; i < out_size; i++) out[i] = loss;
    }
}

// ---------------------------------------------------------------------------
extern "C" void kernel_launch(void* const* d_in, const int* in_sizes, int n_in,
                              void* d_out, int out_size) {
    const float* left = (const float*)d_in[0];
    const float* drug = (const float*)d_in[1];
    const float* sem  = (const float*)d_in[2];
    const float* Wq   = (const float*)d_in[3];
    const float* Wk   = (const float*)d_in[4];
    const float* Wv   = (const float*)d_in[5];
    const int*   ids  = (const int*)d_in[6];
    float* out = (float*)d_out;

    void* p = nullptr;
    cudaGetSymbolAddress(&p, g_scratch);
    Scratch* s = (Scratch*)p;

    const float inv_sqrt_dk = 0.05773502691896258f;  // 1/sqrt(300)

    qkv_proj<<<dim3(4, 32, 3), 256>>>(drug, sem, Wq, Wk, Wv, s->Q, s->K, s->V);
    scores_abar_tf32<<<dim3(32, 16), 256>>>(s->Q, s->K, s->abar, inv_sqrt_dk);
    proto_kernel<<<dim3(NC, 4), 256>>>(s->abar, s->V, s->proto);
    logits_center_ce<<<NB, 256>>>(s->proto, left, ids, s->center, s->nd, s->ce, s->invn);
    gram_rowmax_tf32<<<dim3(6, NB), 256>>>(s->proto, s->center, s->invn, s->rm1p);
    dcos_rowmax<<<NB, 256>>>(s->nd, s->rm2);
    finalize<<<1, 256>>>(s->ce, s->rm1p, s->rm2, out, out_size);
}

// round 10
// speedup vs baseline: 1.1322x; 1.1322x over previous
#include <cuda_runtime.h>
#include <math.h>
#include <stdint.h>

#define NB   128
#define NS1  16
#define NDQ  300
#define NC   256
#define NS2  8
#define ND   256
#define MQ   (NB*NS1) // 2048
#define MK   (NC*NS2) // 2048

struct alignas(128) Scratch {
    float Q[MQ * ND];
    float K[MK * ND];
    float V[MK * ND];
    float abar[(size_t)NB * NC * NS2];  // 128x256x8
    float proto[(size_t)NB * NC * ND];  // 128x256x256
    float center[NB * ND];
    float nd[NB * ND];
    float invn[NB * NC];
    float logits[NB * NC];
    float ce[NB];
    float rm1p[NB * 2 * NC];
    float rm2[NB];
};
__device__ Scratch g_scratch;

// ---------------------------------------------------------------------------
// helpers
// ---------------------------------------------------------------------------
__device__ __forceinline__ uint32_t f2tf32(float x) {
    uint32_t r;
    asm("cvt.rna.tf32.f32 %0, %1;" : "=r"(r) : "f"(x));
    return r;
}
__device__ __forceinline__ void mma_tf32(float* d, const uint32_t* a, uint32_t b0, uint32_t b1) {
    asm volatile(
        "mma.sync.aligned.m16n8k8.row.col.f32.tf32.tf32.f32 "
        "{%0,%1,%2,%3},{%4,%5,%6,%7},{%8,%9},{%0,%1,%2,%3};"
        : "+f"(d[0]), "+f"(d[1]), "+f"(d[2]), "+f"(d[3])
        : "r"(a[0]), "r"(a[1]), "r"(a[2]), "r"(a[3]), "r"(b0), "r"(b1));
}

// exp(x) for x <= 0, FMA pipe only.
__device__ __forceinline__ float fexp(float x) {
    x = fmaxf(x, -80.f);
    const float L2E = 1.4426950408889634f;
    float t = fmaf(x, L2E, 12582912.f);
    float n = t - 12582912.f;
    float f = fmaf(x, L2E, -n);
    float p = 0.0001540353f;
    p = fmaf(p, f, 0.0013333558f);
    p = fmaf(p, f, 0.0096181291f);
    p = fmaf(p, f, 0.0555041087f);
    p = fmaf(p, f, 0.2402265069f);
    p = fmaf(p, f, 0.6931471806f);
    p = fmaf(p, f, 1.0f);
    int ni = (__float_as_int(t) & 0x7FFFFF) - 0x400000;
    return __int_as_float((ni + 127) << 23) * p;
}
__device__ __forceinline__ float frcp(float x) {
    float r = __uint_as_float(0x7EF311C3u - __float_as_uint(x));
    r = r * (2.f - x * r);
    r = r * (2.f - x * r);
    r = r * (2.f - x * r);
    return r;
}

#define GSTR 12

// ---------------------------------------------------------------------------
// Merged QKV projection: one launch, blockIdx.z selects {Q,K,V}.
// 64x64 tiles, 4x4 micro (validated body). grid (4, 32, 3).
// ---------------------------------------------------------------------------
__global__ void qkv_proj(const float* __restrict__ drug, const float* __restrict__ sem,
                         const float* __restrict__ Wq, const float* __restrict__ Wk,
                         const float* __restrict__ Wv, float* __restrict__ Qo,
                         float* __restrict__ Ko, float* __restrict__ Vo) {
    int z = blockIdx.z;
    const float* A = (z == 0) ? drug : sem;
    const float* B = (z == 0) ? Wq : ((z == 1) ? Wk : Wv);
    float* C = (z == 0) ? Qo : ((z == 1) ? Ko : Vo);
    int K = (z == 0) ? NDQ : ND;
    const int N = ND;

    __shared__ float As[64][17];
    __shared__ float Bs[64][17];
    int tid = threadIdx.x;
    int tx = tid & 15, ty = tid >> 4;
    int m0 = blockIdx.y * 64, n0 = blockIdx.x * 64;
    float acc[4][4];
#pragma unroll
    for (int i = 0; i < 4; i++)
#pragma unroll
        for (int j = 0; j < 4; j++) acc[i][j] = 0.f;
    for (int k0 = 0; k0 < K; k0 += 16) {
#pragma unroll
        for (int i = 0; i < 4; i++) {
            int idx = tid + 256 * i;
            int r = idx >> 4, kk = idx & 15;
            int kg = k0 + kk;
            As[r][kk] = (kg < K) ? A[(size_t)(m0 + r) * K + kg] : 0.f;
        }
#pragma unroll
        for (int i = 0; i < 4; i++) {
            int idx = tid + 256 * i;
            int kk = idx >> 6, n = idx & 63;
            int kg = k0 + kk;
            Bs[n][kk] = (kg < K) ? B[(size_t)kg * N + n0 + n] : 0.f;
        }
        __syncthreads();
#pragma unroll
        for (int kk = 0; kk < 16; kk++) {
            float a[4], bb[4];
#pragma unroll
            for (int i = 0; i < 4; i++) a[i] = As[ty * 4 + i][kk];
#pragma unroll
            for (int j = 0; j < 4; j++) bb[j] = Bs[tx * 4 + j][kk];
#pragma unroll
            for (int i = 0; i < 4; i++)
#pragma unroll
                for (int j = 0; j < 4; j++) acc[i][j] += a[i] * bb[j];
        }
        __syncthreads();
    }
#pragma unroll
    for (int i = 0; i < 4; i++)
#pragma unroll
        for (int j = 0; j < 4; j++)
            C[(size_t)(m0 + ty * 4 + i) * N + n0 + tx * 4 + j] = acc[i][j];
}

// ---------------------------------------------------------------------------
// FUSED scores (tf32) + softmax(s2) + mean(s1) -> abar. (round-8 form)
// ---------------------------------------------------------------------------
__global__ __launch_bounds__(256) void scores_abar_tf32(const float* __restrict__ A,
                                                        const float* __restrict__ B,
                                                        float* __restrict__ abar, float alpha) {
    __shared__ uint32_t Ah[128 * GSTR];
    __shared__ uint32_t Bh[128 * GSTR];

    int m0 = blockIdx.y * 128, n0 = blockIdx.x * 128;
    int t = threadIdx.x;
    int w = t >> 5, lane = t & 31;
    int w_row = w >> 1, w_col = w & 1;
    int qrow = lane >> 2, qcol = lane & 3;
    int lrow = t >> 1, lpart = (t & 1) * 4;

    const float* Ag = A + (size_t)(m0 + lrow) * ND + lpart;
    const float* Bg = B + (size_t)(n0 + lrow) * ND + lpart;

    float acc[2][8][4];
#pragma unroll
    for (int mi = 0; mi < 2; mi++)
#pragma unroll
        for (int nt = 0; nt < 8; nt++)
#pragma unroll
            for (int j = 0; j < 4; j++) acc[mi][nt][j] = 0.f;

    float4 pa = *(const float4*)(Ag);
    float4 pb = *(const float4*)(Bg);

    for (int k0 = 0; k0 < ND; k0 += 8) {
        uint32_t* ad = &Ah[lrow * GSTR + lpart];
        ad[0] = f2tf32(pa.x); ad[1] = f2tf32(pa.y);
        ad[2] = f2tf32(pa.z); ad[3] = f2tf32(pa.w);
        uint32_t* bd = &Bh[lrow * GSTR + lpart];
        bd[0] = f2tf32(pb.x); bd[1] = f2tf32(pb.y);
        bd[2] = f2tf32(pb.z); bd[3] = f2tf32(pb.w);
        __syncthreads();
        if (k0 + 8 < ND) {
            pa = *(const float4*)(Ag + k0 + 8);
            pb = *(const float4*)(Bg + k0 + 8);
        }
        uint32_t afr[2][4];
#pragma unroll
        for (int mi = 0; mi < 2; mi++) {
            int mr = w_row * 32 + mi * 16 + qrow;
            afr[mi][0] = Ah[mr * GSTR + qcol];
            afr[mi][1] = Ah[(mr + 8) * GSTR + qcol];
            afr[mi][2] = Ah[mr * GSTR + qcol + 4];
            afr[mi][3] = Ah[(mr + 8) * GSTR + qcol + 4];
        }
#pragma unroll
        for (int nt = 0; nt < 8; nt++) {
            int nr = w_col * 64 + nt * 8 + qrow;
            uint32_t b0 = Bh[nr * GSTR + qcol];
            uint32_t b1 = Bh[nr * GSTR + qcol + 4];
            mma_tf32(acc[0][nt], afr[0], b0, b1);
            mma_tf32(acc[1][nt], afr[1], b0, b1);
        }
        __syncthreads();
    }

    const float inv16 = 1.f / 16.f;
#pragma unroll
    for (int mi = 0; mi < 2; mi++) {
        int b = (m0 >> 4) + w_row * 2 + mi;
#pragma unroll
        for (int nt = 0; nt < 8; nt++) {
            int c = (n0 >> 3) + w_col * 8 + nt;
            float v00 = acc[mi][nt][0] * alpha;
            float v01 = acc[mi][nt][1] * alpha;
            float v10 = acc[mi][nt][2] * alpha;
            float v11 = acc[mi][nt][3] * alpha;
            float mx0 = fmaxf(v00, v01), mx1 = fmaxf(v10, v11);
            mx0 = fmaxf(mx0, __shfl_xor_sync(0xffffffffu, mx0, 1));
            mx0 = fmaxf(mx0, __shfl_xor_sync(0xffffffffu, mx0, 2));
            mx1 = fmaxf(mx1, __shfl_xor_sync(0xffffffffu, mx1, 1));
            mx1 = fmaxf(mx1, __shfl_xor_sync(0xffffffffu, mx1, 2));
            float e00 = fexp(v00 - mx0), e01 = fexp(v01 - mx0);
            float e10 = fexp(v10 - mx1), e11 = fexp(v11 - mx1);
            float s0 = e00 + e01, s1 = e10 + e11;
            s0 += __shfl_xor_sync(0xffffffffu, s0, 1);
            s0 += __shfl_xor_sync(0xffffffffu, s0, 2);
            s1 += __shfl_xor_sync(0xffffffffu, s1, 1);
            s1 += __shfl_xor_sync(0xffffffffu, s1, 2);
            float r0 = frcp(s0), r1 = frcp(s1);
            float a0 = e00 * r0 + e10 * r1;
            float a1 = e01 * r0 + e11 * r1;
            a0 += __shfl_xor_sync(0xffffffffu, a0, 4);
            a1 += __shfl_xor_sync(0xffffffffu, a1, 4);
            a0 += __shfl_xor_sync(0xffffffffu, a0, 8);
            a1 += __shfl_xor_sync(0xffffffffu, a1, 8);
            a0 += __shfl_xor_sync(0xffffffffu, a0, 16);
            a1 += __shfl_xor_sync(0xffffffffu, a1, 16);
            if (qrow == 0) {
                float2 v = make_float2(a0 * inv16, a1 * inv16);
                *(float2*)&abar[((size_t)b * NC + c) * 8 + qcol * 2] = v;
            }
        }
    }
}

// ---------------------------------------------------------------------------
// proto[b,c,:] = sum_t abar[b,c,t] * V[c,t,:]. grid (256 c, 4 btile), 256 thr.
// ---------------------------------------------------------------------------
__global__ void proto_kernel(const float* __restrict__ abar, const float* __restrict__ V,
                             float* __restrict__ proto) {
    int c = blockIdx.x;
    int bt = blockIdx.y;
    int t = threadIdx.x;
    __shared__ float Vs[8][256];
    __shared__ float ab[32][8];

    for (int i = t; i < 8 * 256; i += 256)
        Vs[i >> 8][i & 255] = V[(size_t)c * 8 * 256 + i];
    {
        int bl = t >> 3, j = t & 7;
        ab[bl][j] = abar[((size_t)(bt * 32 + bl) * NC + c) * 8 + j];
    }
    __syncthreads();

#pragma unroll 4
    for (int bl = 0; bl < 32; bl++) {
        float a0 = ab[bl][0], a1 = ab[bl][1], a2 = ab[bl][2], a3 = ab[bl][3];
        float a4 = ab[bl][4], a5 = ab[bl][5], a6 = ab[bl][6], a7 = ab[bl][7];
        float acc = a0 * Vs[0][t] + a1 * Vs[1][t] + a2 * Vs[2][t] + a3 * Vs[3][t]
                  + a4 * Vs[4][t] + a5 * Vs[5][t] + a6 * Vs[6][t] + a7 * Vs[7][t];
        proto[((size_t)(bt * 32 + bl) * NC + c) * ND + t] = acc;
    }
}

// ---------------------------------------------------------------------------
// tf32 Gram + rowmax, SYMMETRIC (3 tiles, round-8 form). grid (3, 128 b).
// ---------------------------------------------------------------------------
__global__ __launch_bounds__(256) void gram_rowmax_tf32(const float* __restrict__ proto,
                                                        const float* __restrict__ center,
                                                        const float* __restrict__ invn,
                                                        float* __restrict__ rm1p) {
    __shared__ uint32_t As[128 * GSTR];
    __shared__ uint32_t Bs[128 * GSTR];
    __shared__ float rmax_s[2][128];
    __shared__ float cmax_s[4][128];

    int tri = blockIdx.x;
    int b = blockIdx.y;
    int rb = (tri == 2) ? 1 : 0;
    int cb = (tri == 0) ? 0 : 1;
    bool offdiag = (tri == 1);
    int r0 = rb * 128, c0 = cb * 128;

    const float* X = proto + (size_t)b * NC * ND;
    const float* ctr = center + b * ND;

    int t = threadIdx.x;
    int w = t >> 5, lane = t & 31;
    int w_row = w >> 1, w_col = w & 1;
    int qrow = lane >> 2, qcol = lane & 3;
    int lrow = t >> 1;
    int lpart = (t & 1) * 4;

    const float* Ag = X + (size_t)(r0 + lrow) * ND + lpart;
    const float* Bg = X + (size_t)(c0 + lrow) * ND + lpart;

    float acc[2][8][4];
#pragma unroll
    for (int mi = 0; mi < 2; mi++)
#pragma unroll
        for (int nt = 0; nt < 8; nt++)
#pragma unroll
            for (int j = 0; j < 4; j++) acc[mi][nt][j] = 0.f;

    float4 pa = *(const float4*)(Ag);
    float4 pb = *(const float4*)(Bg);
    float4 pc = *(const float4*)(ctr + lpart);

    for (int k0 = 0; k0 < ND; k0 += 8) {
        uint32_t* ad = &As[lrow * GSTR + lpart];
        ad[0] = f2tf32(pa.x - pc.x); ad[1] = f2tf32(pa.y - pc.y);
        ad[2] = f2tf32(pa.z - pc.z); ad[3] = f2tf32(pa.w - pc.w);
        uint32_t* bd = &Bs[lrow * GSTR + lpart];
        bd[0] = f2tf32(pb.x - pc.x); bd[1] = f2tf32(pb.y - pc.y);
        bd[2] = f2tf32(pb.z - pc.z); bd[3] = f2tf32(pb.w - pc.w);
        __syncthreads();
        if (k0 + 8 < ND) {
            pa = *(const float4*)(Ag + k0 + 8);
            pb = *(const float4*)(Bg + k0 + 8);
            pc = *(const float4*)(ctr + k0 + 8 + lpart);
        }
        uint32_t afr[2][4];
#pragma unroll
        for (int mi = 0; mi < 2; mi++) {
            int mr = w_row * 32 + mi * 16 + qrow;
            afr[mi][0] = As[mr * GSTR + qcol];
            afr[mi][1] = As[(mr + 8) * GSTR + qcol];
            afr[mi][2] = As[mr * GSTR + qcol + 4];
            afr[mi][3] = As[(mr + 8) * GSTR + qcol + 4];
        }
#pragma unroll
        for (int nt = 0; nt < 8; nt++) {
            int nr = w_col * 64 + nt * 8 + qrow;
            uint32_t b0 = Bs[nr * GSTR + qcol];
            uint32_t b1 = Bs[nr * GSTR + qcol + 4];
            mma_tf32(acc[0][nt], afr[0], b0, b1);
            mma_tf32(acc[1][nt], afr[1], b0, b1);
        }
        __syncthreads();
    }

    const float* invb = invn + b * NC;
    float ir[2][2];
#pragma unroll
    for (int mi = 0; mi < 2; mi++) {
        int r = r0 + w_row * 32 + mi * 16 + qrow;
        ir[mi][0] = invb[r];
        ir[mi][1] = invb[r + 8];
    }
    float ic[8][2];
#pragma unroll
    for (int nt = 0; nt < 8; nt++) {
        int c = c0 + w_col * 64 + nt * 8 + qcol * 2;
        ic[nt][0] = invb[c];
        ic[nt][1] = invb[c + 1];
    }
    float rmx[2][2] = {{-1e30f, -1e30f}, {-1e30f, -1e30f}};
    float cm[8][2];
#pragma unroll
    for (int nt = 0; nt < 8; nt++) { cm[nt][0] = -1e30f; cm[nt][1] = -1e30f; }

#pragma unroll
    for (int mi = 0; mi < 2; mi++)
#pragma unroll
        for (int h = 0; h < 2; h++) {
            int r = r0 + w_row * 32 + mi * 16 + qrow + h * 8;
#pragma unroll
            for (int nt = 0; nt < 8; nt++) {
#pragma unroll
                for (int j = 0; j < 2; j++) {
                    int c = c0 + w_col * 64 + nt * 8 + qcol * 2 + j;
                    float v = acc[mi][nt][h * 2 + j] * ir[mi][h] * ic[nt][j] - (r == c ? 1.f : 0.f);
                    rmx[mi][h] = fmaxf(rmx[mi][h], v);
                    cm[nt][j] = fmaxf(cm[nt][j], v);
                }
            }
        }
#pragma unroll
    for (int off = 1; off < 4; off <<= 1)
#pragma unroll
        for (int mi = 0; mi < 2; mi++)
#pragma unroll
            for (int h = 0; h < 2; h++)
                rmx[mi][h] = fmaxf(rmx[mi][h], __shfl_xor_sync(0xffffffffu, rmx[mi][h], off));
    if (qcol == 0) {
#pragma unroll
        for (int mi = 0; mi < 2; mi++)
#pragma unroll
            for (int h = 0; h < 2; h++)
                rmax_s[w_col][w_row * 32 + mi * 16 + qrow + h * 8] = rmx[mi][h];
    }
    if (offdiag) {
#pragma unroll
        for (int off = 4; off < 32; off <<= 1)
#pragma unroll
            for (int nt = 0; nt < 8; nt++)
#pragma unroll
                for (int j = 0; j < 2; j++)
                    cm[nt][j] = fmaxf(cm[nt][j], __shfl_xor_sync(0xffffffffu, cm[nt][j], off));
        if (qrow == 0) {
#pragma unroll
            for (int nt = 0; nt < 8; nt++)
#pragma unroll
                for (int j = 0; j < 2; j++)
                    cmax_s[w_row][w_col * 64 + nt * 8 + qcol * 2 + j] = cm[nt][j];
        }
    }
    __syncthreads();
    if (t < 128) {
        rm1p[((size_t)b * 2 + cb) * NC + r0 + t] = fmaxf(rmax_s[0][t], rmax_s[1][t]);
        if (offdiag) {
            float v = fmaxf(fmaxf(cmax_s[0][t], cmax_s[1][t]), fmaxf(cmax_s[2][t], cmax_s[3][t]));
            rm1p[((size_t)b * 2 + 0) * NC + 128 + t] = v;
        }
    }
}

// ---------------------------------------------------------------------------
// center + n_d. grid 128, 256 thr.
// ---------------------------------------------------------------------------
__global__ void center_nd(const float* __restrict__ proto, const float* __restrict__ left,
                          float* __restrict__ center, float* __restrict__ nd) {
    int b = blockIdx.x;
    int t = threadIdx.x;
    __shared__ float red[256];
    const float* pb = proto + (size_t)b * 65536;

    float s = 0.f;
#pragma unroll 8
    for (int c = 0; c < 256; c++) s += pb[(size_t)c * 256 + t];
    float ctr = s * (1.f / 256.f);
    center[b * 256 + t] = ctr;

    float v = left[b * 256 + t] - ctr;
    red[t] = v * v;
    __syncthreads();
    for (int off = 128; off > 0; off >>= 1) {
        if (t < off) red[t] += red[t + off];
        __syncthreads();
    }
    float nrm = sqrtf(red[0]);
    nd[b * 256 + t] = v / fmaxf(nrm, 1e-12f);
}

// ---------------------------------------------------------------------------
// logits + invn. grid (4, 128), 256 thr = 8 warps; warp handles 8 classes.
// ---------------------------------------------------------------------------
__global__ void logits_invn(const float* __restrict__ proto, const float* __restrict__ left,
                            const float* __restrict__ center, float* __restrict__ logits,
                            float* __restrict__ invn) {
    int b = blockIdx.y;
    int cblk = blockIdx.x * 64;
    int t = threadIdx.x;
    int w = t >> 5, lane = t & 31;
    const float* pb = proto + (size_t)b * 65536;

    float4 l0 = *(const float4*)&left[b * 256 + lane * 8];
    float4 l1 = *(const float4*)&left[b * 256 + lane * 8 + 4];
    float4 c0 = *(const float4*)&center[b * 256 + lane * 8];
    float4 c1 = *(const float4*)&center[b * 256 + lane * 8 + 4];

#pragma unroll
    for (int cc = 0; cc < 8; cc++) {
        int c = cblk + w * 8 + cc;
        const float* pr = pb + (size_t)c * 256 + lane * 8;
        float4 x0 = *(const float4*)pr;
        float4 x1 = *(const float4*)(pr + 4);
        float d = x0.x * l0.x + x0.y * l0.y + x0.z * l0.z + x0.w * l0.w
                + x1.x * l1.x + x1.y * l1.y + x1.z * l1.z + x1.w * l1.w;
        float dx, sq = 0.f;
        dx = x0.x - c0.x; sq += dx * dx;
        dx = x0.y - c0.y; sq += dx * dx;
        dx = x0.z - c0.z; sq += dx * dx;
        dx = x0.w - c0.w; sq += dx * dx;
        dx = x1.x - c1.x; sq += dx * dx;
        dx = x1.y - c1.y; sq += dx * dx;
        dx = x1.z - c1.z; sq += dx * dx;
        dx = x1.w - c1.w; sq += dx * dx;
#pragma unroll
        for (int off = 16; off > 0; off >>= 1) {
            d += __shfl_xor_sync(0xffffffffu, d, off);
            sq += __shfl_xor_sync(0xffffffffu, sq, off);
        }
        if (lane == 0) {
            logits[b * NC + c] = d * (1.0f / 0.9f);
            invn[b * NC + c] = 1.f / fmaxf(sqrtf(sq), 1e-12f);
        }
    }
}

// ---------------------------------------------------------------------------
// CE from logits. grid 128, 256 thr.
// ---------------------------------------------------------------------------
__global__ void ce_kernel(const float* __restrict__ logits, const int* __restrict__ ids,
                          float* __restrict__ ce_part) {
    int b = blockIdx.x;
    int t = threadIdx.x;
    __shared__ float red[256];
    float lg = logits[b * NC + t];
    red[t] = lg;
    __syncthreads();
    for (int off = 128; off > 0; off >>= 1) {
        if (t < off) red[t] = fmaxf(red[t], red[t + off]);
        __syncthreads();
    }
    float mx = red[0];
    __syncthreads();
    red[t] = expf(lg - mx);
    __syncthreads();
    for (int off = 128; off > 0; off >>= 1) {
        if (t < off) red[t] += red[t + off];
        __syncthreads();
    }
    if (t == 0) {
        float lse = mx + logf(red[0]);
        ce_part[b] = lse - logits[b * NC + ids[b]];
    }
}

// ---------------------------------------------------------------------------
__global__ void dcos_rowmax(const float* __restrict__ nd, float* __restrict__ rowmax2) {
    int i = blockIdx.x;
    int t = threadIdx.x;
    __shared__ float xi[256];
    __shared__ float red[256];
    xi[t] = nd[i * 256 + t];
    __syncthreads();
    float m = -1e30f;
    if (t < 128) {
        float s = 0.f;
        const float* xj = nd + t * 256;
        for (int d = 0; d < 256; d++) s += xi[d] * xj[d];
        m = s - (i == t ? 1.f : 0.f);
    }
    red[t] = m;
    __syncthreads();
    for (int off = 128; off > 0; off >>= 1) {
        if (t < off) red[t] = fmaxf(red[t], red[t + off]);
        __syncthreads();
    }
    if (t == 0) rowmax2[i] = red[0];
}

// ---------------------------------------------------------------------------
__global__ void finalize(const float* __restrict__ ce_part, const float* __restrict__ rm1p,
                         const float* __restrict__ rm2, float* __restrict__ out, int out_size) {
    int t = threadIdx.x;
    __shared__ float ra[256], rb[256], rc[256];
    float a = 0.f, b2 = 0.f, c2 = 0.f;
    for (int i = t; i < 128; i += 256) { a += ce_part[i]; c2 += rm2[i]; }
    for (int i = t; i < 32768; i += 256) {
        int b = i >> 8, r = i & 255;
        float v = fmaxf(rm1p[((size_t)b * 2 + 0) * 256 + r], rm1p[((size_t)b * 2 + 1) * 256 + r]);
        b2 += v;
    }
    ra[t] = a; rb[t] = b2; rc[t] = c2;
    __syncthreads();
    for (int off = 128; off > 0; off >>= 1) {
        if (t < off) {
            ra[t] += ra[t + off];
            rb[t] += rb[t + off];
            rc[t] += rc[t + off];
        }
        __syncthreads();
    }
    if (t == 0) {
        float loss = ra[0] / 128.f + 0.7f * (rb[0] / 32768.f + rc[0] / 128.f);
        for (int i = 0; i < out_size; i++) out[i] = loss;
    }
}

// ---------------------------------------------------------------------------
extern "C" void kernel_launch(void* const* d_in, const int* in_sizes, int n_in,
                              void* d_out, int out_size) {
    const float* left = (const float*)d_in[0];
    const float* drug = (const float*)d_in[1];
    const float* sem  = (const float*)d_in[2];
    const float* Wq   = (const float*)d_in[3];
    const float* Wk   = (const float*)d_in[4];
    const float* Wv   = (const float*)d_in[5];
    const int*   ids  = (const int*)d_in[6];
    float* out = (float*)d_out;

    void* p = nullptr;
    cudaGetSymbolAddress(&p, g_scratch);
    Scratch* s = (Scratch*)p;

    const float inv_sqrt_dk = 0.05773502691896258f;  // 1/sqrt(300)

    qkv_proj<<<dim3(4, 32, 3), 256>>>(drug, sem, Wq, Wk, Wv, s->Q, s->K, s->V);
    scores_abar_tf32<<<dim3(16, 16), 256>>>(s->Q, s->K, s->abar, inv_sqrt_dk);
    proto_kernel<<<dim3(NC, 4), 256>>>(s->abar, s->V, s->proto);
    center_nd<<<NB, 256>>>(s->proto, left, s->center, s->nd);
    logits_invn<<<dim3(4, NB), 256>>>(s->proto, left, s->center, s->logits, s->invn);
    ce_kernel<<<NB, 256>>>(s->logits, ids, s->ce);
    gram_rowmax_tf32<<<dim3(3, NB), 256>>>(s->proto, s->center, s->invn, s->rm1p);
    dcos_rowmax<<<NB, 256>>>(s->nd, s->rm2);
    finalize<<<1, 256>>>(s->ce, s->rm1p, s->rm2, out, out_size);
}

// round 11
// speedup vs baseline: 1.1725x; 1.0356x over previous
#include <cuda_runtime.h>
#include <math.h>
#include <stdint.h>

#define NB   128
#define NS1  16
#define NDQ  300
#define NC   256
#define NS2  8
#define ND   256
#define MQ   (NB*NS1) // 2048
#define MK   (NC*NS2) // 2048

struct alignas(128) Scratch {
    float Q[MQ * ND];
    float K[MK * ND];
    float V[MK * ND];
    float abar[(size_t)NB * NC * NS2];  // 128x256x8
    float proto[(size_t)NB * NC * ND];  // 128x256x256
    float cpart[8 * NB * ND];           // partial column sums
    float center[NB * ND];
    float nd[NB * ND];
    float invn[NB * NC];
    float logits[NB * NC];
    float ce[NB];
    float rm1p[NB * 2 * NC];
    float rm2[NB];
};
__device__ Scratch g_scratch;

// ---------------------------------------------------------------------------
// helpers
// ---------------------------------------------------------------------------
__device__ __forceinline__ uint32_t f2tf32(float x) {
    uint32_t r;
    asm("cvt.rna.tf32.f32 %0, %1;" : "=r"(r) : "f"(x));
    return r;
}
__device__ __forceinline__ void mma_tf32(float* d, const uint32_t* a, uint32_t b0, uint32_t b1) {
    asm volatile(
        "mma.sync.aligned.m16n8k8.row.col.f32.tf32.tf32.f32 "
        "{%0,%1,%2,%3},{%4,%5,%6,%7},{%8,%9},{%0,%1,%2,%3};"
        : "+f"(d[0]), "+f"(d[1]), "+f"(d[2]), "+f"(d[3])
        : "r"(a[0]), "r"(a[1]), "r"(a[2]), "r"(a[3]), "r"(b0), "r"(b1));
}

// exp(x) for x <= 0, FMA pipe only.
__device__ __forceinline__ float fexp(float x) {
    x = fmaxf(x, -80.f);
    const float L2E = 1.4426950408889634f;
    float t = fmaf(x, L2E, 12582912.f);
    float n = t - 12582912.f;
    float f = fmaf(x, L2E, -n);
    float p = 0.0001540353f;
    p = fmaf(p, f, 0.0013333558f);
    p = fmaf(p, f, 0.0096181291f);
    p = fmaf(p, f, 0.0555041087f);
    p = fmaf(p, f, 0.2402265069f);
    p = fmaf(p, f, 0.6931471806f);
    p = fmaf(p, f, 1.0f);
    int ni = (__float_as_int(t) & 0x7FFFFF) - 0x400000;
    return __int_as_float((ni + 127) << 23) * p;
}
__device__ __forceinline__ float frcp(float x) {
    float r = __uint_as_float(0x7EF311C3u - __float_as_uint(x));
    r = r * (2.f - x * r);
    r = r * (2.f - x * r);
    r = r * (2.f - x * r);
    return r;
}

#define GSTR 12

// ---------------------------------------------------------------------------
// Merged QKV projection: one launch, blockIdx.z selects {Q,K,V}.
// ---------------------------------------------------------------------------
__global__ void qkv_proj(const float* __restrict__ drug, const float* __restrict__ sem,
                         const float* __restrict__ Wq, const float* __restrict__ Wk,
                         const float* __restrict__ Wv, float* __restrict__ Qo,
                         float* __restrict__ Ko, float* __restrict__ Vo) {
    int z = blockIdx.z;
    const float* A = (z == 0) ? drug : sem;
    const float* B = (z == 0) ? Wq : ((z == 1) ? Wk : Wv);
    float* C = (z == 0) ? Qo : ((z == 1) ? Ko : Vo);
    int K = (z == 0) ? NDQ : ND;
    const int N = ND;

    __shared__ float As[64][17];
    __shared__ float Bs[64][17];
    int tid = threadIdx.x;
    int tx = tid & 15, ty = tid >> 4;
    int m0 = blockIdx.y * 64, n0 = blockIdx.x * 64;
    float acc[4][4];
#pragma unroll
    for (int i = 0; i < 4; i++)
#pragma unroll
        for (int j = 0; j < 4; j++) acc[i][j] = 0.f;
    for (int k0 = 0; k0 < K; k0 += 16) {
#pragma unroll
        for (int i = 0; i < 4; i++) {
            int idx = tid + 256 * i;
            int r = idx >> 4, kk = idx & 15;
            int kg = k0 + kk;
            As[r][kk] = (kg < K) ? A[(size_t)(m0 + r) * K + kg] : 0.f;
        }
#pragma unroll
        for (int i = 0; i < 4; i++) {
            int idx = tid + 256 * i;
            int kk = idx >> 6, n = idx & 63;
            int kg = k0 + kk;
            Bs[n][kk] = (kg < K) ? B[(size_t)kg * N + n0 + n] : 0.f;
        }
        __syncthreads();
#pragma unroll
        for (int kk = 0; kk < 16; kk++) {
            float a[4], bb[4];
#pragma unroll
            for (int i = 0; i < 4; i++) a[i] = As[ty * 4 + i][kk];
#pragma unroll
            for (int j = 0; j < 4; j++) bb[j] = Bs[tx * 4 + j][kk];
#pragma unroll
            for (int i = 0; i < 4; i++)
#pragma unroll
                for (int j = 0; j < 4; j++) acc[i][j] += a[i] * bb[j];
        }
        __syncthreads();
    }
#pragma unroll
    for (int i = 0; i < 4; i++)
#pragma unroll
        for (int j = 0; j < 4; j++)
            C[(size_t)(m0 + ty * 4 + i) * N + n0 + tx * 4 + j] = acc[i][j];
}

// ---------------------------------------------------------------------------
// FUSED scores (tf32) + softmax(s2) + mean(s1) -> abar. (round-8 form)
// ---------------------------------------------------------------------------
__global__ __launch_bounds__(256) void scores_abar_tf32(const float* __restrict__ A,
                                                        const float* __restrict__ B,
                                                        float* __restrict__ abar, float alpha) {
    __shared__ uint32_t Ah[128 * GSTR];
    __shared__ uint32_t Bh[128 * GSTR];

    int m0 = blockIdx.y * 128, n0 = blockIdx.x * 128;
    int t = threadIdx.x;
    int w = t >> 5, lane = t & 31;
    int w_row = w >> 1, w_col = w & 1;
    int qrow = lane >> 2, qcol = lane & 3;
    int lrow = t >> 1, lpart = (t & 1) * 4;

    const float* Ag = A + (size_t)(m0 + lrow) * ND + lpart;
    const float* Bg = B + (size_t)(n0 + lrow) * ND + lpart;

    float acc[2][8][4];
#pragma unroll
    for (int mi = 0; mi < 2; mi++)
#pragma unroll
        for (int nt = 0; nt < 8; nt++)
#pragma unroll
            for (int j = 0; j < 4; j++) acc[mi][nt][j] = 0.f;

    float4 pa = *(const float4*)(Ag);
    float4 pb = *(const float4*)(Bg);

    for (int k0 = 0; k0 < ND; k0 += 8) {
        uint32_t* ad = &Ah[lrow * GSTR + lpart];
        ad[0] = f2tf32(pa.x); ad[1] = f2tf32(pa.y);
        ad[2] = f2tf32(pa.z); ad[3] = f2tf32(pa.w);
        uint32_t* bd = &Bh[lrow * GSTR + lpart];
        bd[0] = f2tf32(pb.x); bd[1] = f2tf32(pb.y);
        bd[2] = f2tf32(pb.z); bd[3] = f2tf32(pb.w);
        __syncthreads();
        if (k0 + 8 < ND) {
            pa = *(const float4*)(Ag + k0 + 8);
            pb = *(const float4*)(Bg + k0 + 8);
        }
        uint32_t afr[2][4];
#pragma unroll
        for (int mi = 0; mi < 2; mi++) {
            int mr = w_row * 32 + mi * 16 + qrow;
            afr[mi][0] = Ah[mr * GSTR + qcol];
            afr[mi][1] = Ah[(mr + 8) * GSTR + qcol];
            afr[mi][2] = Ah[mr * GSTR + qcol + 4];
            afr[mi][3] = Ah[(mr + 8) * GSTR + qcol + 4];
        }
#pragma unroll
        for (int nt = 0; nt < 8; nt++) {
            int nr = w_col * 64 + nt * 8 + qrow;
            uint32_t b0 = Bh[nr * GSTR + qcol];
            uint32_t b1 = Bh[nr * GSTR + qcol + 4];
            mma_tf32(acc[0][nt], afr[0], b0, b1);
            mma_tf32(acc[1][nt], afr[1], b0, b1);
        }
        __syncthreads();
    }

    const float inv16 = 1.f / 16.f;
#pragma unroll
    for (int mi = 0; mi < 2; mi++) {
        int b = (m0 >> 4) + w_row * 2 + mi;
#pragma unroll
        for (int nt = 0; nt < 8; nt++) {
            int c = (n0 >> 3) + w_col * 8 + nt;
            float v00 = acc[mi][nt][0] * alpha;
            float v01 = acc[mi][nt][1] * alpha;
            float v10 = acc[mi][nt][2] * alpha;
            float v11 = acc[mi][nt][3] * alpha;
            float mx0 = fmaxf(v00, v01), mx1 = fmaxf(v10, v11);
            mx0 = fmaxf(mx0, __shfl_xor_sync(0xffffffffu, mx0, 1));
            mx0 = fmaxf(mx0, __shfl_xor_sync(0xffffffffu, mx0, 2));
            mx1 = fmaxf(mx1, __shfl_xor_sync(0xffffffffu, mx1, 1));
            mx1 = fmaxf(mx1, __shfl_xor_sync(0xffffffffu, mx1, 2));
            float e00 = fexp(v00 - mx0), e01 = fexp(v01 - mx0);
            float e10 = fexp(v10 - mx1), e11 = fexp(v11 - mx1);
            float s0 = e00 + e01, s1 = e10 + e11;
            s0 += __shfl_xor_sync(0xffffffffu, s0, 1);
            s0 += __shfl_xor_sync(0xffffffffu, s0, 2);
            s1 += __shfl_xor_sync(0xffffffffu, s1, 1);
            s1 += __shfl_xor_sync(0xffffffffu, s1, 2);
            float r0 = frcp(s0), r1 = frcp(s1);
            float a0 = e00 * r0 + e10 * r1;
            float a1 = e01 * r0 + e11 * r1;
            a0 += __shfl_xor_sync(0xffffffffu, a0, 4);
            a1 += __shfl_xor_sync(0xffffffffu, a1, 4);
            a0 += __shfl_xor_sync(0xffffffffu, a0, 8);
            a1 += __shfl_xor_sync(0xffffffffu, a1, 8);
            a0 += __shfl_xor_sync(0xffffffffu, a0, 16);
            a1 += __shfl_xor_sync(0xffffffffu, a1, 16);
            if (qrow == 0) {
                float2 v = make_float2(a0 * inv16, a1 * inv16);
                *(float2*)&abar[((size_t)b * NC + c) * 8 + qcol * 2] = v;
            }
        }
    }
}

// ---------------------------------------------------------------------------
// proto[b,c,:] = sum_t abar[b,c,t] * V[c,t,:]. grid (256 c, 4 btile), 256 thr.
// ---------------------------------------------------------------------------
__global__ void proto_kernel(const float* __restrict__ abar, const float* __restrict__ V,
                             float* __restrict__ proto) {
    int c = blockIdx.x;
    int bt = blockIdx.y;
    int t = threadIdx.x;
    __shared__ float Vs[8][256];
    __shared__ float ab[32][8];

    for (int i = t; i < 8 * 256; i += 256)
        Vs[i >> 8][i & 255] = V[(size_t)c * 8 * 256 + i];
    {
        int bl = t >> 3, j = t & 7;
        ab[bl][j] = abar[((size_t)(bt * 32 + bl) * NC + c) * 8 + j];
    }
    __syncthreads();

#pragma unroll 4
    for (int bl = 0; bl < 32; bl++) {
        float a0 = ab[bl][0], a1 = ab[bl][1], a2 = ab[bl][2], a3 = ab[bl][3];
        float a4 = ab[bl][4], a5 = ab[bl][5], a6 = ab[bl][6], a7 = ab[bl][7];
        float acc = a0 * Vs[0][t] + a1 * Vs[1][t] + a2 * Vs[2][t] + a3 * Vs[3][t]
                  + a4 * Vs[4][t] + a5 * Vs[5][t] + a6 * Vs[6][t] + a7 * Vs[7][t];
        proto[((size_t)(bt * 32 + bl) * NC + c) * ND + t] = acc;
    }
}

// ---------------------------------------------------------------------------
// tf32 Gram + rowmax, SYMMETRIC (3 tiles, round-8 form). grid (3, 128 b).
// ---------------------------------------------------------------------------
__global__ __launch_bounds__(256) void gram_rowmax_tf32(const float* __restrict__ proto,
                                                        const float* __restrict__ center,
                                                        const float* __restrict__ invn,
                                                        float* __restrict__ rm1p) {
    __shared__ uint32_t As[128 * GSTR];
    __shared__ uint32_t Bs[128 * GSTR];
    __shared__ float rmax_s[2][128];
    __shared__ float cmax_s[4][128];

    int tri = blockIdx.x;
    int b = blockIdx.y;
    int rb = (tri == 2) ? 1 : 0;
    int cb = (tri == 0) ? 0 : 1;
    bool offdiag = (tri == 1);
    int r0 = rb * 128, c0 = cb * 128;

    const float* X = proto + (size_t)b * NC * ND;
    const float* ctr = center + b * ND;

    int t = threadIdx.x;
    int w = t >> 5, lane = t & 31;
    int w_row = w >> 1, w_col = w & 1;
    int qrow = lane >> 2, qcol = lane & 3;
    int lrow = t >> 1;
    int lpart = (t & 1) * 4;

    const float* Ag = X + (size_t)(r0 + lrow) * ND + lpart;
    const float* Bg = X + (size_t)(c0 + lrow) * ND + lpart;

    float acc[2][8][4];
#pragma unroll
    for (int mi = 0; mi < 2; mi++)
#pragma unroll
        for (int nt = 0; nt < 8; nt++)
#pragma unroll
            for (int j = 0; j < 4; j++) acc[mi][nt][j] = 0.f;

    float4 pa = *(const float4*)(Ag);
    float4 pb = *(const float4*)(Bg);
    float4 pc = *(const float4*)(ctr + lpart);

    for (int k0 = 0; k0 < ND; k0 += 8) {
        uint32_t* ad = &As[lrow * GSTR + lpart];
        ad[0] = f2tf32(pa.x - pc.x); ad[1] = f2tf32(pa.y - pc.y);
        ad[2] = f2tf32(pa.z - pc.z); ad[3] = f2tf32(pa.w - pc.w);
        uint32_t* bd = &Bs[lrow * GSTR + lpart];
        bd[0] = f2tf32(pb.x - pc.x); bd[1] = f2tf32(pb.y - pc.y);
        bd[2] = f2tf32(pb.z - pc.z); bd[3] = f2tf32(pb.w - pc.w);
        __syncthreads();
        if (k0 + 8 < ND) {
            pa = *(const float4*)(Ag + k0 + 8);
            pb = *(const float4*)(Bg + k0 + 8);
            pc = *(const float4*)(ctr + k0 + 8 + lpart);
        }
        uint32_t afr[2][4];
#pragma unroll
        for (int mi = 0; mi < 2; mi++) {
            int mr = w_row * 32 + mi * 16 + qrow;
            afr[mi][0] = As[mr * GSTR + qcol];
            afr[mi][1] = As[(mr + 8) * GSTR + qcol];
            afr[mi][2] = As[mr * GSTR + qcol + 4];
            afr[mi][3] = As[(mr + 8) * GSTR + qcol + 4];
        }
#pragma unroll
        for (int nt = 0; nt < 8; nt++) {
            int nr = w_col * 64 + nt * 8 + qrow;
            uint32_t b0 = Bs[nr * GSTR + qcol];
            uint32_t b1 = Bs[nr * GSTR + qcol + 4];
            mma_tf32(acc[0][nt], afr[0], b0, b1);
            mma_tf32(acc[1][nt], afr[1], b0, b1);
        }
        __syncthreads();
    }

    const float* invb = invn + b * NC;
    float ir[2][2];
#pragma unroll
    for (int mi = 0; mi < 2; mi++) {
        int r = r0 + w_row * 32 + mi * 16 + qrow;
        ir[mi][0] = invb[r];
        ir[mi][1] = invb[r + 8];
    }
    float ic[8][2];
#pragma unroll
    for (int nt = 0; nt < 8; nt++) {
        int c = c0 + w_col * 64 + nt * 8 + qcol * 2;
        ic[nt][0] = invb[c];
        ic[nt][1] = invb[c + 1];
    }
    float rmx[2][2] = {{-1e30f, -1e30f}, {-1e30f, -1e30f}};
    float cm[8][2];
#pragma unroll
    for (int nt = 0; nt < 8; nt++) { cm[nt][0] = -1e30f; cm[nt][1] = -1e30f; }

#pragma unroll
    for (int mi = 0; mi < 2; mi++)
#pragma unroll
        for (int h = 0; h < 2; h++) {
            int r = r0 + w_row * 32 + mi * 16 + qrow + h * 8;
#pragma unroll
            for (int nt = 0; nt < 8; nt++) {
#pragma unroll
                for (int j = 0; j < 2; j++) {
                    int c = c0 + w_col * 64 + nt * 8 + qcol * 2 + j;
                    float v = acc[mi][nt][h * 2 + j] * ir[mi][h] * ic[nt][j] - (r == c ? 1.f : 0.f);
                    rmx[mi][h] = fmaxf(rmx[mi][h], v);
                    cm[nt][j] = fmaxf(cm[nt][j], v);
                }
            }
        }
#pragma unroll
    for (int off = 1; off < 4; off <<= 1)
#pragma unroll
        for (int mi = 0; mi < 2; mi++)
#pragma unroll
            for (int h = 0; h < 2; h++)
                rmx[mi][h] = fmaxf(rmx[mi][h], __shfl_xor_sync(0xffffffffu, rmx[mi][h], off));
    if (qcol == 0) {
#pragma unroll
        for (int mi = 0; mi < 2; mi++)
#pragma unroll
            for (int h = 0; h < 2; h++)
                rmax_s[w_col][w_row * 32 + mi * 16 + qrow + h * 8] = rmx[mi][h];
    }
    if (offdiag) {
#pragma unroll
        for (int off = 4; off < 32; off <<= 1)
#pragma unroll
            for (int nt = 0; nt < 8; nt++)
#pragma unroll
                for (int j = 0; j < 2; j++)
                    cm[nt][j] = fmaxf(cm[nt][j], __shfl_xor_sync(0xffffffffu, cm[nt][j], off));
        if (qrow == 0) {
#pragma unroll
            for (int nt = 0; nt < 8; nt++)
#pragma unroll
                for (int j = 0; j < 2; j++)
                    cmax_s[w_row][w_col * 64 + nt * 8 + qcol * 2 + j] = cm[nt][j];
        }
    }
    __syncthreads();
    if (t < 128) {
        rm1p[((size_t)b * 2 + cb) * NC + r0 + t] = fmaxf(rmax_s[0][t], rmax_s[1][t]);
        if (offdiag) {
            float v = fmaxf(fmaxf(cmax_s[0][t], cmax_s[1][t]), fmaxf(cmax_s[2][t], cmax_s[3][t]));
            rm1p[((size_t)b * 2 + 0) * NC + 128 + t] = v;
        }
    }
}

// ---------------------------------------------------------------------------
// center partial sums: grid (8, 128), block sums 32 classes' rows.
// ---------------------------------------------------------------------------
__global__ void center_partial(const float* __restrict__ proto, float* __restrict__ cpart) {
    int chunk = blockIdx.x;
    int b = blockIdx.y;
    int t = threadIdx.x;
    const float* pb = proto + (size_t)b * 65536 + (size_t)chunk * 32 * 256;
    float s = 0.f;
#pragma unroll 8
    for (int c = 0; c < 32; c++) s += pb[c * 256 + t];
    cpart[((size_t)chunk * NB + b) * ND + t] = s;
}

// ---------------------------------------------------------------------------
// center finalize + n_d. grid 128, 256 thr.
// ---------------------------------------------------------------------------
__global__ void center_nd_final(const float* __restrict__ cpart, const float* __restrict__ left,
                                float* __restrict__ center, float* __restrict__ nd) {
    int b = blockIdx.x;
    int t = threadIdx.x;
    __shared__ float red[256];
    float s = 0.f;
#pragma unroll
    for (int k = 0; k < 8; k++) s += cpart[((size_t)k * NB + b) * ND + t];
    float ctr = s * (1.f / 256.f);
    center[b * 256 + t] = ctr;

    float v = left[b * 256 + t] - ctr;
    red[t] = v * v;
    __syncthreads();
    for (int off = 128; off > 0; off >>= 1) {
        if (t < off) red[t] += red[t + off];
        __syncthreads();
    }
    float nrm = sqrtf(red[0]);
    nd[b * 256 + t] = v / fmaxf(nrm, 1e-12f);
}

// ---------------------------------------------------------------------------
// logits + invn. grid (4, 128), 256 thr = 8 warps; warp handles 8 classes.
// ---------------------------------------------------------------------------
__global__ void logits_invn(const float* __restrict__ proto, const float* __restrict__ left,
                            const float* __restrict__ center, float* __restrict__ logits,
                            float* __restrict__ invn) {
    int b = blockIdx.y;
    int cblk = blockIdx.x * 64;
    int t = threadIdx.x;
    int w = t >> 5, lane = t & 31;
    const float* pb = proto + (size_t)b * 65536;

    float4 l0 = *(const float4*)&left[b * 256 + lane * 8];
    float4 l1 = *(const float4*)&left[b * 256 + lane * 8 + 4];
    float4 c0 = *(const float4*)&center[b * 256 + lane * 8];
    float4 c1 = *(const float4*)&center[b * 256 + lane * 8 + 4];

#pragma unroll
    for (int cc = 0; cc < 8; cc++) {
        int c = cblk + w * 8 + cc;
        const float* pr = pb + (size_t)c * 256 + lane * 8;
        float4 x0 = *(const float4*)pr;
        float4 x1 = *(const float4*)(pr + 4);
        float d = x0.x * l0.x + x0.y * l0.y + x0.z * l0.z + x0.w * l0.w
                + x1.x * l1.x + x1.y * l1.y + x1.z * l1.z + x1.w * l1.w;
        float dx, sq = 0.f;
        dx = x0.x - c0.x; sq += dx * dx;
        dx = x0.y - c0.y; sq += dx * dx;
        dx = x0.z - c0.z; sq += dx * dx;
        dx = x0.w - c0.w; sq += dx * dx;
        dx = x1.x - c1.x; sq += dx * dx;
        dx = x1.y - c1.y; sq += dx * dx;
        dx = x1.z - c1.z; sq += dx * dx;
        dx = x1.w - c1.w; sq += dx * dx;
#pragma unroll
        for (int off = 16; off > 0; off >>= 1) {
            d += __shfl_xor_sync(0xffffffffu, d, off);
            sq += __shfl_xor_sync(0xffffffffu, sq, off);
        }
        if (lane == 0) {
            logits[b * NC + c] = d * (1.0f / 0.9f);
            invn[b * NC + c] = 1.f / fmaxf(sqrtf(sq), 1e-12f);
        }
    }
}

// ---------------------------------------------------------------------------
// CE from logits. grid 128, 256 thr.
// ---------------------------------------------------------------------------
__global__ void ce_kernel(const float* __restrict__ logits, const int* __restrict__ ids,
                          float* __restrict__ ce_part) {
    int b = blockIdx.x;
    int t = threadIdx.x;
    __shared__ float red[256];
    float lg = logits[b * NC + t];
    red[t] = lg;
    __syncthreads();
    for (int off = 128; off > 0; off >>= 1) {
        if (t < off) red[t] = fmaxf(red[t], red[t + off]);
        __syncthreads();
    }
    float mx = red[0];
    __syncthreads();
    red[t] = expf(lg - mx);
    __syncthreads();
    for (int off = 128; off > 0; off >>= 1) {
        if (t < off) red[t] += red[t + off];
        __syncthreads();
    }
    if (t == 0) {
        float lse = mx + logf(red[0]);
        ce_part[b] = lse - logits[b * NC + ids[b]];
    }
}

// ---------------------------------------------------------------------------
__global__ void dcos_rowmax(const float* __restrict__ nd, float* __restrict__ rowmax2) {
    int i = blockIdx.x;
    int t = threadIdx.x;
    __shared__ float xi[256];
    __shared__ float red[256];
    xi[t] = nd[i * 256 + t];
    __syncthreads();
    float m = -1e30f;
    if (t < 128) {
        float s = 0.f;
        const float* xj = nd + t * 256;
        for (int d = 0; d < 256; d++) s += xi[d] * xj[d];
        m = s - (i == t ? 1.f : 0.f);
    }
    red[t] = m;
    __syncthreads();
    for (int off = 128; off > 0; off >>= 1) {
        if (t < off) red[t] = fmaxf(red[t], red[t + off]);
        __syncthreads();
    }
    if (t == 0) rowmax2[i] = red[0];
}

// ---------------------------------------------------------------------------
__global__ void finalize(const float* __restrict__ ce_part, const float* __restrict__ rm1p,
                         const float* __restrict__ rm2, float* __restrict__ out, int out_size) {
    int t = threadIdx.x;
    __shared__ float ra[256], rb[256], rc[256];
    float a = 0.f, b2 = 0.f, c2 = 0.f;
    for (int i = t; i < 128; i += 256) { a += ce_part[i]; c2 += rm2[i]; }
    for (int i = t; i < 32768; i += 256) {
        int b = i >> 8, r = i & 255;
        float v = fmaxf(rm1p[((size_t)b * 2 + 0) * 256 + r], rm1p[((size_t)b * 2 + 1) * 256 + r]);
        b2 += v;
    }
    ra[t] = a; rb[t] = b2; rc[t] = c2;
    __syncthreads();
    for (int off = 128; off > 0; off >>= 1) {
        if (t < off) {
            ra[t] += ra[t + off];
            rb[t] += rb[t + off];
            rc[t] += rc[t + off];
        }
        __syncthreads();
    }
    if (t == 0) {
        float loss = ra[0] / 128.f + 0.7f * (rb[0] / 32768.f + rc[0] / 128.f);
        for (int i = 0; i < out_size; i++) out[i] = loss;
    }
}

// ---------------------------------------------------------------------------
extern "C" void kernel_launch(void* const* d_in, const int* in_sizes, int n_in,
                              void* d_out, int out_size) {
    const float* left = (const float*)d_in[0];
    const float* drug = (const float*)d_in[1];
    const float* sem  = (const float*)d_in[2];
    const float* Wq   = (const float*)d_in[3];
    const float* Wk   = (const float*)d_in[4];
    const float* Wv   = (const float*)d_in[5];
    const int*   ids  = (const int*)d_in[6];
    float* out = (float*)d_out;

    void* p = nullptr;
    cudaGetSymbolAddress(&p, g_scratch);
    Scratch* s = (Scratch*)p;

    const float inv_sqrt_dk = 0.05773502691896258f;  // 1/sqrt(300)

    qkv_proj<<<dim3(4, 32, 3), 256>>>(drug, sem, Wq, Wk, Wv, s->Q, s->K, s->V);
    scores_abar_tf32<<<dim3(16, 16), 256>>>(s->Q, s->K, s->abar, inv_sqrt_dk);
    proto_kernel<<<dim3(NC, 4), 256>>>(s->abar, s->V, s->proto);
    center_partial<<<dim3(8, NB), 256>>>(s->proto, s->cpart);
    center_nd_final<<<NB, 256>>>(s->cpart, left, s->center, s->nd);
    logits_invn<<<dim3(4, NB), 256>>>(s->proto, left, s->center, s->logits, s->invn);
    ce_kernel<<<NB, 256>>>(s->logits, ids, s->ce);
    gram_rowmax_tf32<<<dim3(3, NB), 256>>>(s->proto, s->center, s->invn, s->rm1p);
    dcos_rowmax<<<NB, 256>>>(s->nd, s->rm2);
    finalize<<<1, 256>>>(s->ce, s->rm1p, s->rm2, out, out_size);
}

// round 12
// speedup vs baseline: 1.1978x; 1.0216x over previous
#include <cuda_runtime.h>
#include <math.h>
#include <stdint.h>

#define NB   128
#define NS1  16
#define NDQ  300
#define NC   256
#define NS2  8
#define ND   256
#define MQ   (NB*NS1) // 2048
#define MK   (NC*NS2) // 2048

struct alignas(128) Scratch {
    float Q[MQ * ND];
    float K[MK * ND];
    float V[MK * ND];
    float abar[(size_t)NB * NC * NS2];  // 128x256x8
    float proto[(size_t)NB * NC * ND];  // 128x256x256
    float cpart[8 * NB * ND];           // partial column sums
    float center[NB * ND];
    float nd[NB * ND];
    float invn[NB * NC];
    float logits[NB * NC];
    float ce[NB];
    float rm1p[NB * 2 * NC];
    float rm2[NB];
};
__device__ Scratch g_scratch;

// ---------------------------------------------------------------------------
// helpers
// ---------------------------------------------------------------------------
__device__ __forceinline__ uint32_t f2tf32(float x) {
    uint32_t r;
    asm("cvt.rna.tf32.f32 %0, %1;" : "=r"(r) : "f"(x));
    return r;
}
__device__ __forceinline__ void mma_tf32(float* d, const uint32_t* a, uint32_t b0, uint32_t b1) {
    asm volatile(
        "mma.sync.aligned.m16n8k8.row.col.f32.tf32.tf32.f32 "
        "{%0,%1,%2,%3},{%4,%5,%6,%7},{%8,%9},{%0,%1,%2,%3};"
        : "+f"(d[0]), "+f"(d[1]), "+f"(d[2]), "+f"(d[3])
        : "r"(a[0]), "r"(a[1]), "r"(a[2]), "r"(a[3]), "r"(b0), "r"(b1));
}

// exp(x) for x <= 0, FMA pipe only.
__device__ __forceinline__ float fexp(float x) {
    x = fmaxf(x, -80.f);
    const float L2E = 1.4426950408889634f;
    float t = fmaf(x, L2E, 12582912.f);
    float n = t - 12582912.f;
    float f = fmaf(x, L2E, -n);
    float p = 0.0001540353f;
    p = fmaf(p, f, 0.0013333558f);
    p = fmaf(p, f, 0.0096181291f);
    p = fmaf(p, f, 0.0555041087f);
    p = fmaf(p, f, 0.2402265069f);
    p = fmaf(p, f, 0.6931471806f);
    p = fmaf(p, f, 1.0f);
    int ni = (__float_as_int(t) & 0x7FFFFF) - 0x400000;
    return __int_as_float((ni + 127) << 23) * p;
}
__device__ __forceinline__ float frcp(float x) {
    float r = __uint_as_float(0x7EF311C3u - __float_as_uint(x));
    r = r * (2.f - x * r);
    r = r * (2.f - x * r);
    r = r * (2.f - x * r);
    return r;
}

#define GSTR 12

// ---------------------------------------------------------------------------
// Merged QKV projection: one launch, blockIdx.z selects {Q,K,V}.
// ---------------------------------------------------------------------------
__global__ void qkv_proj(const float* __restrict__ drug, const float* __restrict__ sem,
                         const float* __restrict__ Wq, const float* __restrict__ Wk,
                         const float* __restrict__ Wv, float* __restrict__ Qo,
                         float* __restrict__ Ko, float* __restrict__ Vo) {
    int z = blockIdx.z;
    const float* A = (z == 0) ? drug : sem;
    const float* B = (z == 0) ? Wq : ((z == 1) ? Wk : Wv);
    float* C = (z == 0) ? Qo : ((z == 1) ? Ko : Vo);
    int K = (z == 0) ? NDQ : ND;
    const int N = ND;

    __shared__ float As[64][17];
    __shared__ float Bs[64][17];
    int tid = threadIdx.x;
    int tx = tid & 15, ty = tid >> 4;
    int m0 = blockIdx.y * 64, n0 = blockIdx.x * 64;
    float acc[4][4];
#pragma unroll
    for (int i = 0; i < 4; i++)
#pragma unroll
        for (int j = 0; j < 4; j++) acc[i][j] = 0.f;
    for (int k0 = 0; k0 < K; k0 += 16) {
#pragma unroll
        for (int i = 0; i < 4; i++) {
            int idx = tid + 256 * i;
            int r = idx >> 4, kk = idx & 15;
            int kg = k0 + kk;
            As[r][kk] = (kg < K) ? A[(size_t)(m0 + r) * K + kg] : 0.f;
        }
#pragma unroll
        for (int i = 0; i < 4; i++) {
            int idx = tid + 256 * i;
            int kk = idx >> 6, n = idx & 63;
            int kg = k0 + kk;
            Bs[n][kk] = (kg < K) ? B[(size_t)kg * N + n0 + n] : 0.f;
        }
        __syncthreads();
#pragma unroll
        for (int kk = 0; kk < 16; kk++) {
            float a[4], bb[4];
#pragma unroll
            for (int i = 0; i < 4; i++) a[i] = As[ty * 4 + i][kk];
#pragma unroll
            for (int j = 0; j < 4; j++) bb[j] = Bs[tx * 4 + j][kk];
#pragma unroll
            for (int i = 0; i < 4; i++)
#pragma unroll
                for (int j = 0; j < 4; j++) acc[i][j] += a[i] * bb[j];
        }
        __syncthreads();
    }
#pragma unroll
    for (int i = 0; i < 4; i++)
#pragma unroll
        for (int j = 0; j < 4; j++)
            C[(size_t)(m0 + ty * 4 + i) * N + n0 + tx * 4 + j] = acc[i][j];
}

// ---------------------------------------------------------------------------
// FUSED scores (tf32, raw-truncation load) + softmax(s2) + mean(s1) -> abar.
// Double-buffered BK=8, one sync per iter. grid (16,16), 256 threads.
// ---------------------------------------------------------------------------
__global__ __launch_bounds__(256) void scores_abar_tf32(const float* __restrict__ A,
                                                        const float* __restrict__ B,
                                                        float* __restrict__ abar, float alpha) {
    __shared__ uint32_t Ah[2][128 * GSTR];
    __shared__ uint32_t Bh[2][128 * GSTR];

    int m0 = blockIdx.y * 128, n0 = blockIdx.x * 128;
    int t = threadIdx.x;
    int w = t >> 5, lane = t & 31;
    int w_row = w >> 1, w_col = w & 1;
    int qrow = lane >> 2, qcol = lane & 3;
    int lrow = t >> 1, lpart = (t & 1) * 4;

    const float* Ag = A + (size_t)(m0 + lrow) * ND + lpart;
    const float* Bg = B + (size_t)(n0 + lrow) * ND + lpart;

    float acc[2][8][4];
#pragma unroll
    for (int mi = 0; mi < 2; mi++)
#pragma unroll
        for (int nt = 0; nt < 8; nt++)
#pragma unroll
            for (int j = 0; j < 4; j++) acc[mi][nt][j] = 0.f;

    // prologue: load + store slice 0
    {
        uint4 pa = *(const uint4*)(Ag);
        uint4 pb = *(const uint4*)(Bg);
        uint32_t* ad = &Ah[0][lrow * GSTR + lpart];
        ad[0] = pa.x; ad[1] = pa.y; ad[2] = pa.z; ad[3] = pa.w;
        uint32_t* bd = &Bh[0][lrow * GSTR + lpart];
        bd[0] = pb.x; bd[1] = pb.y; bd[2] = pb.z; bd[3] = pb.w;
    }
    __syncthreads();

    const int NIT = ND / 8;  // 32
    for (int it = 0; it < NIT; ++it) {
        int cur = it & 1;
        uint4 pa, pb;
        if (it + 1 < NIT) {
            pa = *(const uint4*)(Ag + (it + 1) * 8);
            pb = *(const uint4*)(Bg + (it + 1) * 8);
        }
        uint32_t afr[2][4];
#pragma unroll
        for (int mi = 0; mi < 2; mi++) {
            int mr = w_row * 32 + mi * 16 + qrow;
            afr[mi][0] = Ah[cur][mr * GSTR + qcol];
            afr[mi][1] = Ah[cur][(mr + 8) * GSTR + qcol];
            afr[mi][2] = Ah[cur][mr * GSTR + qcol + 4];
            afr[mi][3] = Ah[cur][(mr + 8) * GSTR + qcol + 4];
        }
#pragma unroll
        for (int nt = 0; nt < 8; nt++) {
            int nr = w_col * 64 + nt * 8 + qrow;
            uint32_t b0 = Bh[cur][nr * GSTR + qcol];
            uint32_t b1 = Bh[cur][nr * GSTR + qcol + 4];
            mma_tf32(acc[0][nt], afr[0], b0, b1);
            mma_tf32(acc[1][nt], afr[1], b0, b1);
        }
        if (it + 1 < NIT) {
            int nxt = cur ^ 1;
            uint32_t* ad = &Ah[nxt][lrow * GSTR + lpart];
            ad[0] = pa.x; ad[1] = pa.y; ad[2] = pa.z; ad[3] = pa.w;
            uint32_t* bd = &Bh[nxt][lrow * GSTR + lpart];
            bd[0] = pb.x; bd[1] = pb.y; bd[2] = pb.z; bd[3] = pb.w;
        }
        __syncthreads();
    }

    const float inv16 = 1.f / 16.f;
#pragma unroll
    for (int mi = 0; mi < 2; mi++) {
        int b = (m0 >> 4) + w_row * 2 + mi;
#pragma unroll
        for (int nt = 0; nt < 8; nt++) {
            int c = (n0 >> 3) + w_col * 8 + nt;
            float v00 = acc[mi][nt][0] * alpha;
            float v01 = acc[mi][nt][1] * alpha;
            float v10 = acc[mi][nt][2] * alpha;
            float v11 = acc[mi][nt][3] * alpha;
            float mx0 = fmaxf(v00, v01), mx1 = fmaxf(v10, v11);
            mx0 = fmaxf(mx0, __shfl_xor_sync(0xffffffffu, mx0, 1));
            mx0 = fmaxf(mx0, __shfl_xor_sync(0xffffffffu, mx0, 2));
            mx1 = fmaxf(mx1, __shfl_xor_sync(0xffffffffu, mx1, 1));
            mx1 = fmaxf(mx1, __shfl_xor_sync(0xffffffffu, mx1, 2));
            float e00 = fexp(v00 - mx0), e01 = fexp(v01 - mx0);
            float e10 = fexp(v10 - mx1), e11 = fexp(v11 - mx1);
            float s0 = e00 + e01, s1 = e10 + e11;
            s0 += __shfl_xor_sync(0xffffffffu, s0, 1);
            s0 += __shfl_xor_sync(0xffffffffu, s0, 2);
            s1 += __shfl_xor_sync(0xffffffffu, s1, 1);
            s1 += __shfl_xor_sync(0xffffffffu, s1, 2);
            float r0 = frcp(s0), r1 = frcp(s1);
            float a0 = e00 * r0 + e10 * r1;
            float a1 = e01 * r0 + e11 * r1;
            a0 += __shfl_xor_sync(0xffffffffu, a0, 4);
            a1 += __shfl_xor_sync(0xffffffffu, a1, 4);
            a0 += __shfl_xor_sync(0xffffffffu, a0, 8);
            a1 += __shfl_xor_sync(0xffffffffu, a1, 8);
            a0 += __shfl_xor_sync(0xffffffffu, a0, 16);
            a1 += __shfl_xor_sync(0xffffffffu, a1, 16);
            if (qrow == 0) {
                float2 v = make_float2(a0 * inv16, a1 * inv16);
                *(float2*)&abar[((size_t)b * NC + c) * 8 + qcol * 2] = v;
            }
        }
    }
}

// ---------------------------------------------------------------------------
// proto[b,c,:] = sum_t abar[b,c,t] * V[c,t,:]. grid (256 c, 4 btile), 256 thr.
// ---------------------------------------------------------------------------
__global__ void proto_kernel(const float* __restrict__ abar, const float* __restrict__ V,
                             float* __restrict__ proto) {
    int c = blockIdx.x;
    int bt = blockIdx.y;
    int t = threadIdx.x;
    __shared__ float Vs[8][256];
    __shared__ float ab[32][8];

    for (int i = t; i < 8 * 256; i += 256)
        Vs[i >> 8][i & 255] = V[(size_t)c * 8 * 256 + i];
    {
        int bl = t >> 3, j = t & 7;
        ab[bl][j] = abar[((size_t)(bt * 32 + bl) * NC + c) * 8 + j];
    }
    __syncthreads();

#pragma unroll 4
    for (int bl = 0; bl < 32; bl++) {
        float a0 = ab[bl][0], a1 = ab[bl][1], a2 = ab[bl][2], a3 = ab[bl][3];
        float a4 = ab[bl][4], a5 = ab[bl][5], a6 = ab[bl][6], a7 = ab[bl][7];
        float acc = a0 * Vs[0][t] + a1 * Vs[1][t] + a2 * Vs[2][t] + a3 * Vs[3][t]
                  + a4 * Vs[4][t] + a5 * Vs[5][t] + a6 * Vs[6][t] + a7 * Vs[7][t];
        proto[((size_t)(bt * 32 + bl) * NC + c) * ND + t] = acc;
    }
}

// ---------------------------------------------------------------------------
// tf32 Gram + rowmax, SYMMETRIC (3 tiles), double-buffered BK=8.
// grid (3, 128 b), 256 threads.
// ---------------------------------------------------------------------------
__global__ __launch_bounds__(256) void gram_rowmax_tf32(const float* __restrict__ proto,
                                                        const float* __restrict__ center,
                                                        const float* __restrict__ invn,
                                                        float* __restrict__ rm1p) {
    __shared__ uint32_t As[2][128 * GSTR];
    __shared__ uint32_t Bs[2][128 * GSTR];
    __shared__ float rmax_s[2][128];
    __shared__ float cmax_s[4][128];

    int tri = blockIdx.x;
    int b = blockIdx.y;
    int rb = (tri == 2) ? 1 : 0;
    int cb = (tri == 0) ? 0 : 1;
    bool offdiag = (tri == 1);
    int r0 = rb * 128, c0 = cb * 128;

    const float* X = proto + (size_t)b * NC * ND;
    const float* ctr = center + b * ND;

    int t = threadIdx.x;
    int w = t >> 5, lane = t & 31;
    int w_row = w >> 1, w_col = w & 1;
    int qrow = lane >> 2, qcol = lane & 3;
    int lrow = t >> 1;
    int lpart = (t & 1) * 4;

    const float* Ag = X + (size_t)(r0 + lrow) * ND + lpart;
    const float* Bg = X + (size_t)(c0 + lrow) * ND + lpart;

    float acc[2][8][4];
#pragma unroll
    for (int mi = 0; mi < 2; mi++)
#pragma unroll
        for (int nt = 0; nt < 8; nt++)
#pragma unroll
            for (int j = 0; j < 4; j++) acc[mi][nt][j] = 0.f;

    // prologue
    {
        float4 pa = *(const float4*)(Ag);
        float4 pb = *(const float4*)(Bg);
        float4 pc = *(const float4*)(ctr + lpart);
        uint32_t* ad = &As[0][lrow * GSTR + lpart];
        ad[0] = f2tf32(pa.x - pc.x); ad[1] = f2tf32(pa.y - pc.y);
        ad[2] = f2tf32(pa.z - pc.z); ad[3] = f2tf32(pa.w - pc.w);
        uint32_t* bd = &Bs[0][lrow * GSTR + lpart];
        bd[0] = f2tf32(pb.x - pc.x); bd[1] = f2tf32(pb.y - pc.y);
        bd[2] = f2tf32(pb.z - pc.z); bd[3] = f2tf32(pb.w - pc.w);
    }
    __syncthreads();

    const int NIT = ND / 8;  // 32
    for (int it = 0; it < NIT; ++it) {
        int cur = it & 1;
        float4 pa, pb, pc;
        if (it + 1 < NIT) {
            int kn = (it + 1) * 8;
            pa = *(const float4*)(Ag + kn);
            pb = *(const float4*)(Bg + kn);
            pc = *(const float4*)(ctr + kn + lpart);
        }
        uint32_t afr[2][4];
#pragma unroll
        for (int mi = 0; mi < 2; mi++) {
            int mr = w_row * 32 + mi * 16 + qrow;
            afr[mi][0] = As[cur][mr * GSTR + qcol];
            afr[mi][1] = As[cur][(mr + 8) * GSTR + qcol];
            afr[mi][2] = As[cur][mr * GSTR + qcol + 4];
            afr[mi][3] = As[cur][(mr + 8) * GSTR + qcol + 4];
        }
#pragma unroll
        for (int nt = 0; nt < 8; nt++) {
            int nr = w_col * 64 + nt * 8 + qrow;
            uint32_t b0 = Bs[cur][nr * GSTR + qcol];
            uint32_t b1 = Bs[cur][nr * GSTR + qcol + 4];
            mma_tf32(acc[0][nt], afr[0], b0, b1);
            mma_tf32(acc[1][nt], afr[1], b0, b1);
        }
        if (it + 1 < NIT) {
            int nxt = cur ^ 1;
            uint32_t* ad = &As[nxt][lrow * GSTR + lpart];
            ad[0] = f2tf32(pa.x - pc.x); ad[1] = f2tf32(pa.y - pc.y);
            ad[2] = f2tf32(pa.z - pc.z); ad[3] = f2tf32(pa.w - pc.w);
            uint32_t* bd = &Bs[nxt][lrow * GSTR + lpart];
            bd[0] = f2tf32(pb.x - pc.x); bd[1] = f2tf32(pb.y - pc.y);
            bd[2] = f2tf32(pb.z - pc.z); bd[3] = f2tf32(pb.w - pc.w);
        }
        __syncthreads();
    }

    const float* invb = invn + b * NC;
    float ir[2][2];
#pragma unroll
    for (int mi = 0; mi < 2; mi++) {
        int r = r0 + w_row * 32 + mi * 16 + qrow;
        ir[mi][0] = invb[r];
        ir[mi][1] = invb[r + 8];
    }
    float ic[8][2];
#pragma unroll
    for (int nt = 0; nt < 8; nt++) {
        int c = c0 + w_col * 64 + nt * 8 + qcol * 2;
        ic[nt][0] = invb[c];
        ic[nt][1] = invb[c + 1];
    }
    float rmx[2][2] = {{-1e30f, -1e30f}, {-1e30f, -1e30f}};
    float cm[8][2];
#pragma unroll
    for (int nt = 0; nt < 8; nt++) { cm[nt][0] = -1e30f; cm[nt][1] = -1e30f; }

#pragma unroll
    for (int mi = 0; mi < 2; mi++)
#pragma unroll
        for (int h = 0; h < 2; h++) {
            int r = r0 + w_row * 32 + mi * 16 + qrow + h * 8;
#pragma unroll
            for (int nt = 0; nt < 8; nt++) {
#pragma unroll
                for (int j = 0; j < 2; j++) {
                    int c = c0 + w_col * 64 + nt * 8 + qcol * 2 + j;
                    float v = acc[mi][nt][h * 2 + j] * ir[mi][h] * ic[nt][j] - (r == c ? 1.f : 0.f);
                    rmx[mi][h] = fmaxf(rmx[mi][h], v);
                    cm[nt][j] = fmaxf(cm[nt][j], v);
                }
            }
        }
#pragma unroll
    for (int off = 1; off < 4; off <<= 1)
#pragma unroll
        for (int mi = 0; mi < 2; mi++)
#pragma unroll
            for (int h = 0; h < 2; h++)
                rmx[mi][h] = fmaxf(rmx[mi][h], __shfl_xor_sync(0xffffffffu, rmx[mi][h], off));
    if (qcol == 0) {
#pragma unroll
        for (int mi = 0; mi < 2; mi++)
#pragma unroll
            for (int h = 0; h < 2; h++)
                rmax_s[w_col][w_row * 32 + mi * 16 + qrow + h * 8] = rmx[mi][h];
    }
    if (offdiag) {
#pragma unroll
        for (int off = 4; off < 32; off <<= 1)
#pragma unroll
            for (int nt = 0; nt < 8; nt++)
#pragma unroll
                for (int j = 0; j < 2; j++)
                    cm[nt][j] = fmaxf(cm[nt][j], __shfl_xor_sync(0xffffffffu, cm[nt][j], off));
        if (qrow == 0) {
#pragma unroll
            for (int nt = 0; nt < 8; nt++)
#pragma unroll
                for (int j = 0; j < 2; j++)
                    cmax_s[w_row][w_col * 64 + nt * 8 + qcol * 2 + j] = cm[nt][j];
        }
    }
    __syncthreads();
    if (t < 128) {
        rm1p[((size_t)b * 2 + cb) * NC + r0 + t] = fmaxf(rmax_s[0][t], rmax_s[1][t]);
        if (offdiag) {
            float v = fmaxf(fmaxf(cmax_s[0][t], cmax_s[1][t]), fmaxf(cmax_s[2][t], cmax_s[3][t]));
            rm1p[((size_t)b * 2 + 0) * NC + 128 + t] = v;
        }
    }
}

// ---------------------------------------------------------------------------
// center partial sums: grid (8, 128), block sums 32 classes' rows.
// ---------------------------------------------------------------------------
__global__ void center_partial(const float* __restrict__ proto, float* __restrict__ cpart) {
    int chunk = blockIdx.x;
    int b = blockIdx.y;
    int t = threadIdx.x;
    const float* pb = proto + (size_t)b * 65536 + (size_t)chunk * 32 * 256;
    float s = 0.f;
#pragma unroll 8
    for (int c = 0; c < 32; c++) s += pb[c * 256 + t];
    cpart[((size_t)chunk * NB + b) * ND + t] = s;
}

// ---------------------------------------------------------------------------
// center finalize + n_d. grid 128, 256 thr.
// ---------------------------------------------------------------------------
__global__ void center_nd_final(const float* __restrict__ cpart, const float* __restrict__ left,
                                float* __restrict__ center, float* __restrict__ nd) {
    int b = blockIdx.x;
    int t = threadIdx.x;
    __shared__ float red[256];
    float s = 0.f;
#pragma unroll
    for (int k = 0; k < 8; k++) s += cpart[((size_t)k * NB + b) * ND + t];
    float ctr = s * (1.f / 256.f);
    center[b * 256 + t] = ctr;

    float v = left[b * 256 + t] - ctr;
    red[t] = v * v;
    __syncthreads();
    for (int off = 128; off > 0; off >>= 1) {
        if (t < off) red[t] += red[t + off];
        __syncthreads();
    }
    float nrm = sqrtf(red[0]);
    nd[b * 256 + t] = v / fmaxf(nrm, 1e-12f);
}

// ---------------------------------------------------------------------------
// logits + invn. grid (4, 128), 256 thr = 8 warps; warp handles 8 classes.
// ---------------------------------------------------------------------------
__global__ void logits_invn(const float* __restrict__ proto, const float* __restrict__ left,
                            const float* __restrict__ center, float* __restrict__ logits,
                            float* __restrict__ invn) {
    int b = blockIdx.y;
    int cblk = blockIdx.x * 64;
    int t = threadIdx.x;
    int w = t >> 5, lane = t & 31;
    const float* pb = proto + (size_t)b * 65536;

    float4 l0 = *(const float4*)&left[b * 256 + lane * 8];
    float4 l1 = *(const float4*)&left[b * 256 + lane * 8 + 4];
    float4 c0 = *(const float4*)&center[b * 256 + lane * 8];
    float4 c1 = *(const float4*)&center[b * 256 + lane * 8 + 4];

#pragma unroll
    for (int cc = 0; cc < 8; cc++) {
        int c = cblk + w * 8 + cc;
        const float* pr = pb + (size_t)c * 256 + lane * 8;
        float4 x0 = *(const float4*)pr;
        float4 x1 = *(const float4*)(pr + 4);
        float d = x0.x * l0.x + x0.y * l0.y + x0.z * l0.z + x0.w * l0.w
                + x1.x * l1.x + x1.y * l1.y + x1.z * l1.z + x1.w * l1.w;
        float dx, sq = 0.f;
        dx = x0.x - c0.x; sq += dx * dx;
        dx = x0.y - c0.y; sq += dx * dx;
        dx = x0.z - c0.z; sq += dx * dx;
        dx = x0.w - c0.w; sq += dx * dx;
        dx = x1.x - c1.x; sq += dx * dx;
        dx = x1.y - c1.y; sq += dx * dx;
        dx = x1.z - c1.z; sq += dx * dx;
        dx = x1.w - c1.w; sq += dx * dx;
#pragma unroll
        for (int off = 16; off > 0; off >>= 1) {
            d += __shfl_xor_sync(0xffffffffu, d, off);
            sq += __shfl_xor_sync(0xffffffffu, sq, off);
        }
        if (lane == 0) {
            logits[b * NC + c] = d * (1.0f / 0.9f);
            invn[b * NC + c] = 1.f / fmaxf(sqrtf(sq), 1e-12f);
        }
    }
}

// ---------------------------------------------------------------------------
// CE from logits. grid 128, 256 thr.
// ---------------------------------------------------------------------------
__global__ void ce_kernel(const float* __restrict__ logits, const int* __restrict__ ids,
                          float* __restrict__ ce_part) {
    int b = blockIdx.x;
    int t = threadIdx.x;
    __shared__ float red[256];
    float lg = logits[b * NC + t];
    red[t] = lg;
    __syncthreads();
    for (int off = 128; off > 0; off >>= 1) {
        if (t < off) red[t] = fmaxf(red[t], red[t + off]);
        __syncthreads();
    }
    float mx = red[0];
    __syncthreads();
    red[t] = expf(lg - mx);
    __syncthreads();
    for (int off = 128; off > 0; off >>= 1) {
        if (t < off) red[t] += red[t + off];
        __syncthreads();
    }
    if (t == 0) {
        float lse = mx + logf(red[0]);
        ce_part[b] = lse - logits[b * NC + ids[b]];
    }
}

// ---------------------------------------------------------------------------
__global__ void dcos_rowmax(const float* __restrict__ nd, float* __restrict__ rowmax2) {
    int i = blockIdx.x;
    int t = threadIdx.x;
    __shared__ float xi[256];
    __shared__ float red[256];
    xi[t] = nd[i * 256 + t];
    __syncthreads();
    float m = -1e30f;
    if (t < 128) {
        float s = 0.f;
        const float* xj = nd + t * 256;
        for (int d = 0; d < 256; d++) s += xi[d] * xj[d];
        m = s - (i == t ? 1.f : 0.f);
    }
    red[t] = m;
    __syncthreads();
    for (int off = 128; off > 0; off >>= 1) {
        if (t < off) red[t] = fmaxf(red[t], red[t + off]);
        __syncthreads();
    }
    if (t == 0) rowmax2[i] = red[0];
}

// ---------------------------------------------------------------------------
__global__ void finalize(const float* __restrict__ ce_part, const float* __restrict__ rm1p,
                         const float* __restrict__ rm2, float* __restrict__ out, int out_size) {
    int t = threadIdx.x;
    __shared__ float ra[256], rb[256], rc[256];
    float a = 0.f, b2 = 0.f, c2 = 0.f;
    for (int i = t; i < 128; i += 256) { a += ce_part[i]; c2 += rm2[i]; }
    for (int i = t; i < 32768; i += 256) {
        int b = i >> 8, r = i & 255;
        float v = fmaxf(rm1p[((size_t)b * 2 + 0) * 256 + r], rm1p[((size_t)b * 2 + 1) * 256 + r]);
        b2 += v;
    }
    ra[t] = a; rb[t] = b2; rc[t] = c2;
    __syncthreads();
    for (int off = 128; off > 0; off >>= 1) {
        if (t < off) {
            ra[t] += ra[t + off];
            rb[t] += rb[t + off];
            rc[t] += rc[t + off];
        }
        __syncthreads();
    }
    if (t == 0) {
        float loss = ra[0] / 128.f + 0.7f * (rb[0] / 32768.f + rc[0] / 128.f);
        for (int i = 0; i < out_size; i++) out[i] = loss;
    }
}

// ---------------------------------------------------------------------------
extern "C" void kernel_launch(void* const* d_in, const int* in_sizes, int n_in,
                              void* d_out, int out_size) {
    const float* left = (const float*)d_in[0];
    const float* drug = (const float*)d_in[1];
    const float* sem  = (const float*)d_in[2];
    const float* Wq   = (const float*)d_in[3];
    const float* Wk   = (const float*)d_in[4];
    const float* Wv   = (const float*)d_in[5];
    const int*   ids  = (const int*)d_in[6];
    float* out = (float*)d_out;

    void* p = nullptr;
    cudaGetSymbolAddress(&p, g_scratch);
    Scratch* s = (Scratch*)p;

    const float inv_sqrt_dk = 0.05773502691896258f;  // 1/sqrt(300)

    qkv_proj<<<dim3(4, 32, 3), 256>>>(drug, sem, Wq, Wk, Wv, s->Q, s->K, s->V);
    scores_abar_tf32<<<dim3(16, 16), 256>>>(s->Q, s->K, s->abar, inv_sqrt_dk);
    proto_kernel<<<dim3(NC, 4), 256>>>(s->abar, s->V, s->proto);
    center_partial<<<dim3(8, NB), 256>>>(s->proto, s->cpart);
    center_nd_final<<<NB, 256>>>(s->cpart, left, s->center, s->nd);
    logits_invn<<<dim3(4, NB), 256>>>(s->proto, left, s->center, s->logits, s->invn);
    ce_kernel<<<NB, 256>>>(s->logits, ids, s->ce);
    gram_rowmax_tf32<<<dim3(3, NB), 256>>>(s->proto, s->center, s->invn, s->rm1p);
    dcos_rowmax<<<NB, 256>>>(s->nd, s->rm2);
    finalize<<<1, 256>>>(s->ce, s->rm1p, s->rm2, out, out_size);
}